// round 5
// baseline (speedup 1.0000x reference)
#include <cuda_runtime.h>
#include <cuda_bf16.h>
#include <cstdint>

// ---------------------------------------------------------------------------
// WindowAttentionConvRpe: B=4096 windows, N=49, DIM=192, NH=6, HD=32, T=169.
//   K0 : split weights (transposed [N][K]) and x into bf16 hi/lo
//   K1 : QKV = X @ qkv_w + qkv_b          (mma.sync bf16 3-term split)
//   K2a: BIAS = [q;k] . gathered-RPE GEMM (SIMT)
//   K2b: attention (fp32 softmax), obuf written as bf16 hi/lo
//   K3 : OUT = O @ proj_w + proj_b        (mma.sync bf16 3-term split)
// NOTE: tcgen05 is NOT available (harness PTX target is sm_103, not sm_103a);
// using sm_80-class mma.sync HMMA instead.
// ---------------------------------------------------------------------------

#define B_WIN   4096
#define NTOK    49
#define DIMC    192
#define NHEAD   6
#define HDIM    32
#define TSZ     169
#define TOKENS  (B_WIN * NTOK)
#define QKVCOLS (3 * DIMC)
#define QSCALE  0.17677669529663687f

__device__ float g_qkv [(size_t)TOKENS * QKVCOLS];
__device__ float g_bias[(size_t)B_WIN * NHEAD * NTOK * NTOK];
__device__ __nv_bfloat16 g_x_hi [(size_t)TOKENS * DIMC];
__device__ __nv_bfloat16 g_x_lo [(size_t)TOKENS * DIMC];
__device__ __nv_bfloat16 g_obuf_hi[(size_t)TOKENS * DIMC];
__device__ __nv_bfloat16 g_obuf_lo[(size_t)TOKENS * DIMC];
__device__ __nv_bfloat16 g_wqkv_hi[QKVCOLS * DIMC];   // [576][192] transposed
__device__ __nv_bfloat16 g_wqkv_lo[QKVCOLS * DIMC];
__device__ __nv_bfloat16 g_wproj_hi[DIMC * DIMC];     // [192][192] transposed
__device__ __nv_bfloat16 g_wproj_lo[DIMC * DIMC];

// ======================= K0a: weight transpose + split =====================
__global__ void splitw_kernel(const float* __restrict__ w,
                              __nv_bfloat16* __restrict__ thi,
                              __nv_bfloat16* __restrict__ tlo, int K, int N)
{
    int i = blockIdx.x * 256 + threadIdx.x;
    if (i >= K * N) return;
    int n = i / K, k = i % K;
    float v = w[(size_t)k * N + n];
    __nv_bfloat16 h = __float2bfloat16(v);
    thi[i] = h;
    tlo[i] = __float2bfloat16(v - __bfloat162float(h));
}

// ======================= K0b: activation split (same layout) ===============
__global__ void splitf_kernel(const float* __restrict__ src,
                              __nv_bfloat16* __restrict__ hi,
                              __nv_bfloat16* __restrict__ lo, int n4)
{
    int i = blockIdx.x * 256 + threadIdx.x;
    if (i >= n4) return;
    float4 v = ((const float4*)src)[i];
    float vv[4] = {v.x, v.y, v.z, v.w};
    union { uint2 q; __nv_bfloat16 h[4]; } H, L;
    #pragma unroll
    for (int e = 0; e < 4; e++) {
        H.h[e] = __float2bfloat16(vv[e]);
        L.h[e] = __float2bfloat16(vv[e] - __bfloat162float(H.h[e]));
    }
    ((uint2*)hi)[i] = H.q;
    ((uint2*)lo)[i] = L.q;
}

// ======================= mma.sync helper ===================================
__device__ __forceinline__ void mma_bf16(float* d, const uint32_t* a,
                                         const uint32_t* b)
{
    asm volatile(
        "mma.sync.aligned.m16n8k16.row.col.f32.bf16.bf16.f32 "
        "{%0,%1,%2,%3}, {%4,%5,%6,%7}, {%8,%9}, {%0,%1,%2,%3};"
        : "+f"(d[0]), "+f"(d[1]), "+f"(d[2]), "+f"(d[3])
        : "r"(a[0]), "r"(a[1]), "r"(a[2]), "r"(a[3]),
          "r"(b[0]), "r"(b[1]));
}

// ======================= K1/K3: HMMA split GEMM ============================
// C[M][Nld] = A[M][192] @ Bt[N][192]^T + bias; cols < scale_limit get *scale.
// Block 128M x 64N, 8 warps (4M x 2N), warp tile 32x32 (2 m16 x 4 n8).
// Fragments LDG'd directly from global (no smem); K fixed at 192.
__global__ __launch_bounds__(256) void mma_gemm_kernel(
    const __nv_bfloat16* __restrict__ Ahi, const __nv_bfloat16* __restrict__ Alo,
    const __nv_bfloat16* __restrict__ Bhi, const __nv_bfloat16* __restrict__ Blo,
    const float* __restrict__ bias, float* __restrict__ C,
    int Nld, int scale_limit, float scale)
{
    const int tid  = threadIdx.x;
    const int lane = tid & 31;
    const int wid  = tid >> 5;
    const int warpM = wid & 3;
    const int warpN = wid >> 2;
    const int g   = lane >> 2;
    const int tig = lane & 3;
    const int m0 = blockIdx.y * 128 + warpM * 32;
    const int n0 = blockIdx.x * 64  + warpN * 32;

    float acc[2][4][4];
    #pragma unroll
    for (int mt = 0; mt < 2; mt++)
        #pragma unroll
        for (int nt = 0; nt < 4; nt++)
            #pragma unroll
            for (int e = 0; e < 4; e++) acc[mt][nt][e] = 0.0f;

    const size_t aoff = (size_t)(m0 + g) * 192 + 2 * tig;
    const size_t boff = (size_t)(n0 + g) * 192 + 2 * tig;

    #pragma unroll 4
    for (int k0 = 0; k0 < 192; k0 += 16) {
        uint32_t ahi[2][4], alo[2][4], bhi[4][2], blo[4][2];
        #pragma unroll
        for (int mt = 0; mt < 2; mt++) {
            const __nv_bfloat16* ph = Ahi + aoff + (size_t)mt * 16 * 192 + k0;
            const __nv_bfloat16* pl = Alo + aoff + (size_t)mt * 16 * 192 + k0;
            ahi[mt][0] = *(const uint32_t*)(ph);
            ahi[mt][1] = *(const uint32_t*)(ph + 8 * 192);
            ahi[mt][2] = *(const uint32_t*)(ph + 8);
            ahi[mt][3] = *(const uint32_t*)(ph + 8 * 192 + 8);
            alo[mt][0] = *(const uint32_t*)(pl);
            alo[mt][1] = *(const uint32_t*)(pl + 8 * 192);
            alo[mt][2] = *(const uint32_t*)(pl + 8);
            alo[mt][3] = *(const uint32_t*)(pl + 8 * 192 + 8);
        }
        #pragma unroll
        for (int nt = 0; nt < 4; nt++) {
            const __nv_bfloat16* ph = Bhi + boff + (size_t)nt * 8 * 192 + k0;
            const __nv_bfloat16* pl = Blo + boff + (size_t)nt * 8 * 192 + k0;
            bhi[nt][0] = *(const uint32_t*)(ph);
            bhi[nt][1] = *(const uint32_t*)(ph + 8);
            blo[nt][0] = *(const uint32_t*)(pl);
            blo[nt][1] = *(const uint32_t*)(pl + 8);
        }
        #pragma unroll
        for (int mt = 0; mt < 2; mt++)
            #pragma unroll
            for (int nt = 0; nt < 4; nt++) {
                mma_bf16(acc[mt][nt], ahi[mt], bhi[nt]);
                mma_bf16(acc[mt][nt], ahi[mt], blo[nt]);
                mma_bf16(acc[mt][nt], alo[mt], bhi[nt]);
            }
    }

    // epilogue: c0,c1 -> (row, col..col+1); c2,c3 -> (row+8, col..col+1)
    #pragma unroll
    for (int mt = 0; mt < 2; mt++) {
        int row = m0 + mt * 16 + g;
        #pragma unroll
        for (int nt = 0; nt < 4; nt++) {
            int col = n0 + nt * 8 + 2 * tig;
            float b0 = bias[col], b1 = bias[col + 1];
            float c0 = acc[mt][nt][0] + b0;
            float c1 = acc[mt][nt][1] + b1;
            float c2 = acc[mt][nt][2] + b0;
            float c3 = acc[mt][nt][3] + b1;
            if (col < scale_limit) {
                c0 *= scale; c1 *= scale; c2 *= scale; c3 *= scale;
            }
            *(float2*)(C + (size_t)row * Nld + col)       = make_float2(c0, c1);
            *(float2*)(C + (size_t)(row + 8) * Nld + col) = make_float2(c2, c3);
        }
    }
}

// ======================= K2a: bias GEMM (SIMT) =============================
__global__ __launch_bounds__(256) void bias_kernel(
    const float* __restrict__ q_rpe, const float* __restrict__ k_rpe)
{
    __shared__ float A_s[64][128];
    __shared__ float G_s[64][64];

    const int hi = blockIdx.x;
    const int h  = hi / NTOK;
    const int i  = hi % NTOK;
    const int ri = i / 7, ci = i % 7;
    const int m0 = blockIdx.y * 128;
    const int tid = threadIdx.x;

    for (int f = tid; f < 8 * 128; f += 256) {
        int bl = f & 127;
        int g4 = f >> 7;
        size_t row = ((size_t)(m0 + bl) * NTOK + i) * QKVCOLS + h * HDIM;
        float4 qv = *(const float4*)(g_qkv + row + g4 * 4);
        A_s[g4 * 4 + 0][bl] = qv.x; A_s[g4 * 4 + 1][bl] = qv.y;
        A_s[g4 * 4 + 2][bl] = qv.z; A_s[g4 * 4 + 3][bl] = qv.w;
        float4 kv = *(const float4*)(g_qkv + row + DIMC + g4 * 4);
        A_s[32 + g4 * 4 + 0][bl] = kv.x; A_s[32 + g4 * 4 + 1][bl] = kv.y;
        A_s[32 + g4 * 4 + 2][bl] = kv.z; A_s[32 + g4 * 4 + 3][bl] = kv.w;
    }
    for (int f = tid; f < 64 * 64; f += 256) {
        int d = f >> 6, j = f & 63;
        float val = 0.0f;
        if (j < NTOK) {
            int t = (ri - j / 7 + 6) * 13 + (ci - j % 7 + 6);
            val = (d < HDIM) ? q_rpe[(h * HDIM + d) * TSZ + t]
                             : k_rpe[(h * HDIM + (d - 32)) * TSZ + t];
        }
        G_s[d][j] = val;
    }
    __syncthreads();

    const int tx = tid & 7;
    const int ty = tid >> 3;

    float acc[4][8];
    #pragma unroll
    for (int r = 0; r < 4; r++)
        #pragma unroll
        for (int c = 0; c < 8; c++) acc[r][c] = 0.0f;

    #pragma unroll 16
    for (int d = 0; d < 64; d++) {
        float4 a4 = *(float4*)&A_s[d][ty * 4];
        float4 g0 = *(float4*)&G_s[d][tx * 8];
        float4 g1 = *(float4*)&G_s[d][tx * 8 + 4];
        float a[4] = {a4.x, a4.y, a4.z, a4.w};
        float g[8] = {g0.x, g0.y, g0.z, g0.w, g1.x, g1.y, g1.z, g1.w};
        #pragma unroll
        for (int r = 0; r < 4; r++)
            #pragma unroll
            for (int c = 0; c < 8; c++)
                acc[r][c] += a[r] * g[c];
    }

    #pragma unroll
    for (int r = 0; r < 4; r++) {
        int bw = m0 + ty * 4 + r;
        size_t base = (((size_t)bw * NHEAD + h) * NTOK + i) * NTOK;
        #pragma unroll
        for (int c = 0; c < 8; c++) {
            int j = tx * 8 + c;
            if (j < NTOK) g_bias[base + j] = acc[r][c];
        }
    }
}

// ======================= K2b: attention ====================================
__global__ __launch_bounds__(256) void attn2_kernel(
    const float* __restrict__ mask, float* __restrict__ attn_out)
{
    __shared__ float q_s[49 * 32];
    __shared__ float v_s[49 * 32];
    __shared__ float p_s[49 * 52];

    const int h = blockIdx.x;
    const int b = blockIdx.y;
    const int tid  = threadIdx.x;
    const int lane = tid & 31;
    const int warp = tid >> 5;

    for (int f = tid; f < 49 * 8; f += 256) {
        int i = f >> 3, c4 = (f & 7) * 4;
        size_t row = ((size_t)b * NTOK + i) * QKVCOLS + h * HDIM;
        *(float4*)(q_s + i * 32 + c4) = *(const float4*)(g_qkv + row + c4);
        *(float4*)(v_s + i * 32 + c4) = *(const float4*)(g_qkv + row + 2 * DIMC + c4);
    }
    float4 kr1[8], kr2[8];
    {
        const int j2c = min(32 + lane, 48);
        const float* kp1 = g_qkv + ((size_t)b * NTOK + lane) * QKVCOLS + DIMC + h * HDIM;
        const float* kp2 = g_qkv + ((size_t)b * NTOK + j2c ) * QKVCOLS + DIMC + h * HDIM;
        #pragma unroll
        for (int c = 0; c < 8; c++) {
            kr1[c] = *(const float4*)(kp1 + c * 4);
            kr2[c] = *(const float4*)(kp2 + c * 4);
        }
    }
    __syncthreads();

    const float* mrow0 = mask + (size_t)(b & 63) * (49 * 49);
    const float* brow0 = g_bias + ((size_t)b * NHEAD + h) * (49 * 49);
    float* attn_b = attn_out + ((size_t)b * NHEAD + h) * (49 * 49);
    const bool has2 = (lane < 17);
    const int j1 = lane, j2 = lane + 32;
    const int nrows = (warp == 0) ? 7 : 6;

    #pragma unroll 1
    for (int r = 0; r < nrows; r++) {
        const int i = warp + r * 8;
        float acc1 = 0.0f, acc2 = 0.0f;
        #pragma unroll
        for (int c = 0; c < 8; c++) {
            float4 q4 = *(const float4*)(q_s + i * 32 + c * 4);
            acc1 += q4.x * kr1[c].x + q4.y * kr1[c].y
                  + q4.z * kr1[c].z + q4.w * kr1[c].w;
            acc2 += q4.x * kr2[c].x + q4.y * kr2[c].y
                  + q4.z * kr2[c].z + q4.w * kr2[c].w;
        }
        acc1 += brow0[i * 49 + j1] + mrow0[i * 49 + j1];
        if (has2) acc2 += brow0[i * 49 + j2] + mrow0[i * 49 + j2];

        float mx = has2 ? fmaxf(acc1, acc2) : acc1;
        #pragma unroll
        for (int o = 16; o > 0; o >>= 1)
            mx = fmaxf(mx, __shfl_xor_sync(0xffffffffu, mx, o));
        float e1 = __expf(acc1 - mx);
        float e2 = has2 ? __expf(acc2 - mx) : 0.0f;
        float sum = e1 + e2;
        #pragma unroll
        for (int o = 16; o > 0; o >>= 1)
            sum += __shfl_xor_sync(0xffffffffu, sum, o);
        float inv = 1.0f / sum;
        float p1 = e1 * inv, p2 = e2 * inv;

        p_s[i * 52 + j1]    = p1;
        attn_b[i * 49 + j1] = p1;
        if (has2) { p_s[i * 52 + j2] = p2; attn_b[i * 49 + j2] = p2; }
    }
    __syncwarp();

    float o[7];
    #pragma unroll
    for (int r = 0; r < 7; r++) o[r] = 0.0f;

    #pragma unroll 1
    for (int j4 = 0; j4 < 12; j4++) {
        float v0 = v_s[(j4 * 4 + 0) * 32 + lane];
        float v1 = v_s[(j4 * 4 + 1) * 32 + lane];
        float v2 = v_s[(j4 * 4 + 2) * 32 + lane];
        float v3 = v_s[(j4 * 4 + 3) * 32 + lane];
        for (int r = 0; r < nrows; r++) {
            float4 p4 = *(const float4*)&p_s[(warp + r * 8) * 52 + j4 * 4];
            o[r] += p4.x * v0 + p4.y * v1 + p4.z * v2 + p4.w * v3;
        }
    }
    {
        float v48 = v_s[48 * 32 + lane];
        for (int r = 0; r < nrows; r++)
            o[r] += p_s[(warp + r * 8) * 52 + 48] * v48;
    }
    for (int r = 0; r < nrows; r++) {
        int i = warp + r * 8;
        size_t idx = ((size_t)b * NTOK + i) * DIMC + h * HDIM + lane;
        float ov = o[r];
        __nv_bfloat16 hi = __float2bfloat16(ov);
        g_obuf_hi[idx] = hi;
        g_obuf_lo[idx] = __float2bfloat16(ov - __bfloat162float(hi));
    }
}

// ---------------------------------------------------------------------------
extern "C" void kernel_launch(void* const* d_in, const int* in_sizes, int n_in,
                              void* d_out, int out_size)
{
    const float* x      = (const float*)d_in[0];
    const float* mask   = (const float*)d_in[1];
    const float* qkv_w  = (const float*)d_in[2];
    const float* qkv_b  = (const float*)d_in[3];
    const float* q_rpe  = (const float*)d_in[4];
    const float* k_rpe  = (const float*)d_in[5];
    const float* proj_w = (const float*)d_in[6];
    const float* proj_b = (const float*)d_in[7];
    // d_in[8] = rpe_indices: recomputed analytically in-kernel

    float* out  = (float*)d_out;
    float* attn = out + (size_t)TOKENS * DIMC;

    void *qkv_p, *xhi, *xlo, *whq, *wlq, *whp, *wlp, *ohi, *olo;
    cudaGetSymbolAddress(&qkv_p, g_qkv);
    cudaGetSymbolAddress(&xhi, g_x_hi);
    cudaGetSymbolAddress(&xlo, g_x_lo);
    cudaGetSymbolAddress(&whq, g_wqkv_hi);
    cudaGetSymbolAddress(&wlq, g_wqkv_lo);
    cudaGetSymbolAddress(&whp, g_wproj_hi);
    cudaGetSymbolAddress(&wlp, g_wproj_lo);
    cudaGetSymbolAddress(&ohi, g_obuf_hi);
    cudaGetSymbolAddress(&olo, g_obuf_lo);

    // K0: splits
    splitw_kernel<<<(DIMC * QKVCOLS + 255) / 256, 256>>>(
        qkv_w, (__nv_bfloat16*)whq, (__nv_bfloat16*)wlq, DIMC, QKVCOLS);
    splitw_kernel<<<(DIMC * DIMC + 255) / 256, 256>>>(
        proj_w, (__nv_bfloat16*)whp, (__nv_bfloat16*)wlp, DIMC, DIMC);
    {
        int n4 = TOKENS * DIMC / 4;
        splitf_kernel<<<(n4 + 255) / 256, 256>>>(
            x, (__nv_bfloat16*)xhi, (__nv_bfloat16*)xlo, n4);
    }

    // K1: QKV projection (HMMA) — q cols pre-scaled
    {
        dim3 grid(QKVCOLS / 64, TOKENS / 128);
        mma_gemm_kernel<<<grid, 256>>>(
            (const __nv_bfloat16*)xhi, (const __nv_bfloat16*)xlo,
            (const __nv_bfloat16*)whq, (const __nv_bfloat16*)wlq,
            qkv_b, (float*)qkv_p, QKVCOLS, DIMC, QSCALE);
    }
    // K2a: bias GEMM
    {
        dim3 grid(NHEAD * NTOK, B_WIN / 128);
        bias_kernel<<<grid, 256>>>(q_rpe, k_rpe);
    }
    // K2b: attention
    {
        dim3 grid(NHEAD, B_WIN);
        attn2_kernel<<<grid, 256>>>(mask, attn);
    }
    // K3: output projection (HMMA)
    {
        dim3 grid(DIMC / 64, TOKENS / 128);
        mma_gemm_kernel<<<grid, 256>>>(
            (const __nv_bfloat16*)ohi, (const __nv_bfloat16*)olo,
            (const __nv_bfloat16*)whp, (const __nv_bfloat16*)wlp,
            proj_b, out, DIMC, 0, 1.0f);
    }
}

// round 6
// speedup vs baseline: 1.4909x; 1.4909x over previous
#include <cuda_runtime.h>
#include <cuda_bf16.h>
#include <cstdint>

// ---------------------------------------------------------------------------
// WindowAttentionConvRpe: B=4096 windows, N=49, DIM=192, NH=6, HD=32, T=169.
//   K0 : split weights (transposed [N][K]) and x into bf16 hi/lo
//   K1 : QKV = X @ qkv_w + qkv_b          (HMMA bf16 3-term split, smem+ldmatrix)
//   K2a: BIAS = [q;k] . gathered-RPE GEMM (SIMT)
//   K2b: attention (fp32 softmax), obuf written as bf16 hi/lo
//   K3 : OUT = O @ proj_w + proj_b        (HMMA)
// tcgen05 unavailable (PTX target sm_103 w/o 'a'); mma.sync path instead.
// ---------------------------------------------------------------------------

#define B_WIN   4096
#define NTOK    49
#define DIMC    192
#define NHEAD   6
#define HDIM    32
#define TSZ     169
#define TOKENS  (B_WIN * NTOK)
#define QKVCOLS (3 * DIMC)
#define QSCALE  0.17677669529663687f

__device__ float g_qkv [(size_t)TOKENS * QKVCOLS];
__device__ float g_bias[(size_t)B_WIN * NHEAD * NTOK * NTOK];
__device__ __nv_bfloat16 g_x_hi [(size_t)TOKENS * DIMC];
__device__ __nv_bfloat16 g_x_lo [(size_t)TOKENS * DIMC];
__device__ __nv_bfloat16 g_obuf_hi[(size_t)TOKENS * DIMC];
__device__ __nv_bfloat16 g_obuf_lo[(size_t)TOKENS * DIMC];
__device__ __nv_bfloat16 g_wqkv_hi[QKVCOLS * DIMC];   // [576][192] transposed
__device__ __nv_bfloat16 g_wqkv_lo[QKVCOLS * DIMC];
__device__ __nv_bfloat16 g_wproj_hi[DIMC * DIMC];     // [192][192] transposed
__device__ __nv_bfloat16 g_wproj_lo[DIMC * DIMC];

// ======================= K0a: weight transpose + split =====================
__global__ void splitw_kernel(const float* __restrict__ w,
                              __nv_bfloat16* __restrict__ thi,
                              __nv_bfloat16* __restrict__ tlo, int K, int N)
{
    int i = blockIdx.x * 256 + threadIdx.x;
    if (i >= K * N) return;
    int n = i / K, k = i % K;
    float v = w[(size_t)k * N + n];
    __nv_bfloat16 h = __float2bfloat16(v);
    thi[i] = h;
    tlo[i] = __float2bfloat16(v - __bfloat162float(h));
}

// ======================= K0b: activation split =============================
__global__ void splitf_kernel(const float* __restrict__ src,
                              __nv_bfloat16* __restrict__ hi,
                              __nv_bfloat16* __restrict__ lo, int n4)
{
    int i = blockIdx.x * 256 + threadIdx.x;
    if (i >= n4) return;
    float4 v = ((const float4*)src)[i];
    float vv[4] = {v.x, v.y, v.z, v.w};
    union { uint2 q; __nv_bfloat16 h[4]; } H, L;
    #pragma unroll
    for (int e = 0; e < 4; e++) {
        H.h[e] = __float2bfloat16(vv[e]);
        L.h[e] = __float2bfloat16(vv[e] - __bfloat162float(H.h[e]));
    }
    ((uint2*)hi)[i] = H.q;
    ((uint2*)lo)[i] = L.q;
}

// ======================= mma / ldmatrix helpers ============================
__device__ __forceinline__ void mma_bf16(float* d, const uint32_t* a,
                                         const uint32_t* b)
{
    asm volatile(
        "mma.sync.aligned.m16n8k16.row.col.f32.bf16.bf16.f32 "
        "{%0,%1,%2,%3}, {%4,%5,%6,%7}, {%8,%9}, {%0,%1,%2,%3};"
        : "+f"(d[0]), "+f"(d[1]), "+f"(d[2]), "+f"(d[3])
        : "r"(a[0]), "r"(a[1]), "r"(a[2]), "r"(a[3]),
          "r"(b[0]), "r"(b[1]));
}
__device__ __forceinline__ void ldsm_x4(uint32_t* r, uint32_t saddr)
{
    asm volatile("ldmatrix.sync.aligned.m8n8.x4.shared.b16 {%0,%1,%2,%3}, [%4];"
        : "=r"(r[0]), "=r"(r[1]), "=r"(r[2]), "=r"(r[3]) : "r"(saddr));
}
__device__ __forceinline__ uint32_t smem_u32(const void* p) {
    uint32_t a;
    asm("{ .reg .u64 t; cvta.to.shared.u64 t, %1; cvt.u32.u64 %0, t; }"
        : "=r"(a) : "l"(p));
    return a;
}

// ======================= K1/K3: HMMA split GEMM (smem + ldmatrix) ==========
// C[M][Nld] = A[M][192] @ Bt[N][192]^T + bias; cols < scale_limit get *scale.
// Block 128M x 64N, 8 warps (4M x 2N), warp tile 32x32. BK=32, 6 k-iters.
// Rows padded to 40 bf16 (20-bank stride -> conflict-free ldmatrix).
#define APAD 40
__global__ __launch_bounds__(256) void mma_gemm_kernel(
    const __nv_bfloat16* __restrict__ Ahi, const __nv_bfloat16* __restrict__ Alo,
    const __nv_bfloat16* __restrict__ Bhi, const __nv_bfloat16* __restrict__ Blo,
    const float* __restrict__ bias, float* __restrict__ C,
    int Nld, int scale_limit, float scale)
{
    __shared__ __align__(16) __nv_bfloat16 sAh[128 * APAD];
    __shared__ __align__(16) __nv_bfloat16 sAl[128 * APAD];
    __shared__ __align__(16) __nv_bfloat16 sBh[64 * APAD];
    __shared__ __align__(16) __nv_bfloat16 sBl[64 * APAD];

    const int tid  = threadIdx.x;
    const int lane = tid & 31;
    const int wid  = tid >> 5;
    const int warpM = wid & 3;
    const int warpN = wid >> 2;
    const int g   = lane >> 2;
    const int tig = lane & 3;
    const int m0 = blockIdx.y * 128;
    const int n0 = blockIdx.x * 64;

    float acc[2][4][4];
    #pragma unroll
    for (int mt = 0; mt < 2; mt++)
        #pragma unroll
        for (int nt = 0; nt < 4; nt++)
            #pragma unroll
            for (int e = 0; e < 4; e++) acc[mt][nt][e] = 0.0f;

    // ldmatrix per-lane source rows/cols
    const int rofA = ((lane >> 3) & 1) * 8 + (lane & 7);
    const int kofA = ((lane >> 4) & 1) * 8;
    const int rofB = ((lane >> 4) & 1) * 8 + (lane & 7);
    const int kofB = ((lane >> 3) & 1) * 8;

    const uint32_t aHiB = smem_u32(sAh) + ((warpM * 32 + rofA) * APAD + kofA) * 2;
    const uint32_t aLoB = smem_u32(sAl) + ((warpM * 32 + rofA) * APAD + kofA) * 2;
    const uint32_t bHiB = smem_u32(sBh) + ((warpN * 32 + rofB) * APAD + kofB) * 2;
    const uint32_t bLoB = smem_u32(sBl) + ((warpN * 32 + rofB) * APAD + kofB) * 2;

    for (int k0 = 0; k0 < 192; k0 += 32) {
        // ---- stage A (128x32) and B (64x32), hi+lo, uint4 chunks ----
        #pragma unroll
        for (int r = 0; r < 2; r++) {
            int c = tid + r * 256;
            int row = c >> 2, u = c & 3;
            size_t src = (size_t)(m0 + row) * 192 + k0 + u * 8;
            *(uint4*)(sAh + row * APAD + u * 8) = *(const uint4*)(Ahi + src);
            *(uint4*)(sAl + row * APAD + u * 8) = *(const uint4*)(Alo + src);
        }
        {
            int row = tid >> 2, u = tid & 3;
            size_t src = (size_t)(n0 + row) * 192 + k0 + u * 8;
            *(uint4*)(sBh + row * APAD + u * 8) = *(const uint4*)(Bhi + src);
            *(uint4*)(sBl + row * APAD + u * 8) = *(const uint4*)(Blo + src);
        }
        __syncthreads();

        #pragma unroll
        for (int s = 0; s < 2; s++) {
            uint32_t ahi[2][4], alo[2][4], bhi[2][4], blo[2][4];
            #pragma unroll
            for (int mt = 0; mt < 2; mt++) {
                uint32_t off = (uint32_t)((mt * 16 * APAD + s * 16) * 2);
                ldsm_x4(ahi[mt], aHiB + off);
                ldsm_x4(alo[mt], aLoB + off);
            }
            #pragma unroll
            for (int p = 0; p < 2; p++) {
                uint32_t off = (uint32_t)((p * 16 * APAD + s * 16) * 2);
                ldsm_x4(bhi[p], bHiB + off);
                ldsm_x4(blo[p], bLoB + off);
            }
            #pragma unroll
            for (int mt = 0; mt < 2; mt++)
                #pragma unroll
                for (int nt = 0; nt < 4; nt++) {
                    const uint32_t* bh = &bhi[nt >> 1][(nt & 1) * 2];
                    const uint32_t* bl = &blo[nt >> 1][(nt & 1) * 2];
                    mma_bf16(acc[mt][nt], ahi[mt], bh);
                    mma_bf16(acc[mt][nt], ahi[mt], bl);
                    mma_bf16(acc[mt][nt], alo[mt], bh);
                }
        }
        __syncthreads();
    }

    // epilogue: c0,c1 -> (row, col..col+1); c2,c3 -> (row+8, ...)
    #pragma unroll
    for (int mt = 0; mt < 2; mt++) {
        int row = m0 + warpM * 32 + mt * 16 + g;
        #pragma unroll
        for (int nt = 0; nt < 4; nt++) {
            int col = n0 + warpN * 32 + nt * 8 + 2 * tig;
            float b0 = bias[col], b1 = bias[col + 1];
            float c0 = acc[mt][nt][0] + b0;
            float c1 = acc[mt][nt][1] + b1;
            float c2 = acc[mt][nt][2] + b0;
            float c3 = acc[mt][nt][3] + b1;
            if (col < scale_limit) {
                c0 *= scale; c1 *= scale; c2 *= scale; c3 *= scale;
            }
            *(float2*)(C + (size_t)row * Nld + col)       = make_float2(c0, c1);
            *(float2*)(C + (size_t)(row + 8) * Nld + col) = make_float2(c2, c3);
        }
    }
}

// ======================= K2a: bias GEMM (SIMT) =============================
__global__ __launch_bounds__(256) void bias_kernel(
    const float* __restrict__ q_rpe, const float* __restrict__ k_rpe)
{
    __shared__ float A_s[64][128];
    __shared__ float G_s[64][64];

    const int hi = blockIdx.x;
    const int h  = hi / NTOK;
    const int i  = hi % NTOK;
    const int ri = i / 7, ci = i % 7;
    const int m0 = blockIdx.y * 128;
    const int tid = threadIdx.x;

    for (int f = tid; f < 8 * 128; f += 256) {
        int bl = f & 127;
        int g4 = f >> 7;
        size_t row = ((size_t)(m0 + bl) * NTOK + i) * QKVCOLS + h * HDIM;
        float4 qv = *(const float4*)(g_qkv + row + g4 * 4);
        A_s[g4 * 4 + 0][bl] = qv.x; A_s[g4 * 4 + 1][bl] = qv.y;
        A_s[g4 * 4 + 2][bl] = qv.z; A_s[g4 * 4 + 3][bl] = qv.w;
        float4 kv = *(const float4*)(g_qkv + row + DIMC + g4 * 4);
        A_s[32 + g4 * 4 + 0][bl] = kv.x; A_s[32 + g4 * 4 + 1][bl] = kv.y;
        A_s[32 + g4 * 4 + 2][bl] = kv.z; A_s[32 + g4 * 4 + 3][bl] = kv.w;
    }
    for (int f = tid; f < 64 * 64; f += 256) {
        int d = f >> 6, j = f & 63;
        float val = 0.0f;
        if (j < NTOK) {
            int t = (ri - j / 7 + 6) * 13 + (ci - j % 7 + 6);
            val = (d < HDIM) ? q_rpe[(h * HDIM + d) * TSZ + t]
                             : k_rpe[(h * HDIM + (d - 32)) * TSZ + t];
        }
        G_s[d][j] = val;
    }
    __syncthreads();

    const int tx = tid & 7;
    const int ty = tid >> 3;

    float acc[4][8];
    #pragma unroll
    for (int r = 0; r < 4; r++)
        #pragma unroll
        for (int c = 0; c < 8; c++) acc[r][c] = 0.0f;

    #pragma unroll 16
    for (int d = 0; d < 64; d++) {
        float4 a4 = *(float4*)&A_s[d][ty * 4];
        float4 g0 = *(float4*)&G_s[d][tx * 8];
        float4 g1 = *(float4*)&G_s[d][tx * 8 + 4];
        float a[4] = {a4.x, a4.y, a4.z, a4.w};
        float g[8] = {g0.x, g0.y, g0.z, g0.w, g1.x, g1.y, g1.z, g1.w};
        #pragma unroll
        for (int r = 0; r < 4; r++)
            #pragma unroll
            for (int c = 0; c < 8; c++)
                acc[r][c] += a[r] * g[c];
    }

    #pragma unroll
    for (int r = 0; r < 4; r++) {
        int bw = m0 + ty * 4 + r;
        size_t base = (((size_t)bw * NHEAD + h) * NTOK + i) * NTOK;
        #pragma unroll
        for (int c = 0; c < 8; c++) {
            int j = tx * 8 + c;
            if (j < NTOK) g_bias[base + j] = acc[r][c];
        }
    }
}

// ======================= K2b: attention ====================================
__global__ __launch_bounds__(256) void attn2_kernel(
    const float* __restrict__ mask, float* __restrict__ attn_out)
{
    __shared__ float q_s[49 * 32];
    __shared__ float v_s[49 * 32];
    __shared__ float p_s[49 * 52];

    const int h = blockIdx.x;
    const int b = blockIdx.y;
    const int tid  = threadIdx.x;
    const int lane = tid & 31;
    const int warp = tid >> 5;

    for (int f = tid; f < 49 * 8; f += 256) {
        int i = f >> 3, c4 = (f & 7) * 4;
        size_t row = ((size_t)b * NTOK + i) * QKVCOLS + h * HDIM;
        *(float4*)(q_s + i * 32 + c4) = *(const float4*)(g_qkv + row + c4);
        *(float4*)(v_s + i * 32 + c4) = *(const float4*)(g_qkv + row + 2 * DIMC + c4);
    }
    float4 kr1[8], kr2[8];
    {
        const int j2c = min(32 + lane, 48);
        const float* kp1 = g_qkv + ((size_t)b * NTOK + lane) * QKVCOLS + DIMC + h * HDIM;
        const float* kp2 = g_qkv + ((size_t)b * NTOK + j2c ) * QKVCOLS + DIMC + h * HDIM;
        #pragma unroll
        for (int c = 0; c < 8; c++) {
            kr1[c] = *(const float4*)(kp1 + c * 4);
            kr2[c] = *(const float4*)(kp2 + c * 4);
        }
    }
    __syncthreads();

    const float* mrow0 = mask + (size_t)(b & 63) * (49 * 49);
    const float* brow0 = g_bias + ((size_t)b * NHEAD + h) * (49 * 49);
    float* attn_b = attn_out + ((size_t)b * NHEAD + h) * (49 * 49);
    const bool has2 = (lane < 17);
    const int j1 = lane, j2 = lane + 32;
    const int nrows = (warp == 0) ? 7 : 6;

    #pragma unroll 1
    for (int r = 0; r < nrows; r++) {
        const int i = warp + r * 8;
        float acc1 = 0.0f, acc2 = 0.0f;
        #pragma unroll
        for (int c = 0; c < 8; c++) {
            float4 q4 = *(const float4*)(q_s + i * 32 + c * 4);
            acc1 += q4.x * kr1[c].x + q4.y * kr1[c].y
                  + q4.z * kr1[c].z + q4.w * kr1[c].w;
            acc2 += q4.x * kr2[c].x + q4.y * kr2[c].y
                  + q4.z * kr2[c].z + q4.w * kr2[c].w;
        }
        acc1 += brow0[i * 49 + j1] + mrow0[i * 49 + j1];
        if (has2) acc2 += brow0[i * 49 + j2] + mrow0[i * 49 + j2];

        float mx = has2 ? fmaxf(acc1, acc2) : acc1;
        #pragma unroll
        for (int o = 16; o > 0; o >>= 1)
            mx = fmaxf(mx, __shfl_xor_sync(0xffffffffu, mx, o));
        float e1 = __expf(acc1 - mx);
        float e2 = has2 ? __expf(acc2 - mx) : 0.0f;
        float sum = e1 + e2;
        #pragma unroll
        for (int o = 16; o > 0; o >>= 1)
            sum += __shfl_xor_sync(0xffffffffu, sum, o);
        float inv = 1.0f / sum;
        float p1 = e1 * inv, p2 = e2 * inv;

        p_s[i * 52 + j1]    = p1;
        attn_b[i * 49 + j1] = p1;
        if (has2) { p_s[i * 52 + j2] = p2; attn_b[i * 49 + j2] = p2; }
    }
    __syncwarp();

    float o[7];
    #pragma unroll
    for (int r = 0; r < 7; r++) o[r] = 0.0f;

    #pragma unroll 1
    for (int j4 = 0; j4 < 12; j4++) {
        float v0 = v_s[(j4 * 4 + 0) * 32 + lane];
        float v1 = v_s[(j4 * 4 + 1) * 32 + lane];
        float v2 = v_s[(j4 * 4 + 2) * 32 + lane];
        float v3 = v_s[(j4 * 4 + 3) * 32 + lane];
        for (int r = 0; r < nrows; r++) {
            float4 p4 = *(const float4*)&p_s[(warp + r * 8) * 52 + j4 * 4];
            o[r] += p4.x * v0 + p4.y * v1 + p4.z * v2 + p4.w * v3;
        }
    }
    {
        float v48 = v_s[48 * 32 + lane];
        for (int r = 0; r < nrows; r++)
            o[r] += p_s[(warp + r * 8) * 52 + 48] * v48;
    }
    for (int r = 0; r < nrows; r++) {
        int i = warp + r * 8;
        size_t idx = ((size_t)b * NTOK + i) * DIMC + h * HDIM + lane;
        float ov = o[r];
        __nv_bfloat16 hi = __float2bfloat16(ov);
        g_obuf_hi[idx] = hi;
        g_obuf_lo[idx] = __float2bfloat16(ov - __bfloat162float(hi));
    }
}

// ---------------------------------------------------------------------------
extern "C" void kernel_launch(void* const* d_in, const int* in_sizes, int n_in,
                              void* d_out, int out_size)
{
    const float* x      = (const float*)d_in[0];
    const float* mask   = (const float*)d_in[1];
    const float* qkv_w  = (const float*)d_in[2];
    const float* qkv_b  = (const float*)d_in[3];
    const float* q_rpe  = (const float*)d_in[4];
    const float* k_rpe  = (const float*)d_in[5];
    const float* proj_w = (const float*)d_in[6];
    const float* proj_b = (const float*)d_in[7];
    // d_in[8] = rpe_indices: recomputed analytically in-kernel

    float* out  = (float*)d_out;
    float* attn = out + (size_t)TOKENS * DIMC;

    void *qkv_p, *xhi, *xlo, *whq, *wlq, *whp, *wlp, *ohi, *olo;
    cudaGetSymbolAddress(&qkv_p, g_qkv);
    cudaGetSymbolAddress(&xhi, g_x_hi);
    cudaGetSymbolAddress(&xlo, g_x_lo);
    cudaGetSymbolAddress(&whq, g_wqkv_hi);
    cudaGetSymbolAddress(&wlq, g_wqkv_lo);
    cudaGetSymbolAddress(&whp, g_wproj_hi);
    cudaGetSymbolAddress(&wlp, g_wproj_lo);
    cudaGetSymbolAddress(&ohi, g_obuf_hi);
    cudaGetSymbolAddress(&olo, g_obuf_lo);

    // K0: splits
    splitw_kernel<<<(DIMC * QKVCOLS + 255) / 256, 256>>>(
        qkv_w, (__nv_bfloat16*)whq, (__nv_bfloat16*)wlq, DIMC, QKVCOLS);
    splitw_kernel<<<(DIMC * DIMC + 255) / 256, 256>>>(
        proj_w, (__nv_bfloat16*)whp, (__nv_bfloat16*)wlp, DIMC, DIMC);
    {
        int n4 = TOKENS * DIMC / 4;
        splitf_kernel<<<(n4 + 255) / 256, 256>>>(
            x, (__nv_bfloat16*)xhi, (__nv_bfloat16*)xlo, n4);
    }

    // K1: QKV projection (HMMA) — q cols pre-scaled
    {
        dim3 grid(QKVCOLS / 64, TOKENS / 128);
        mma_gemm_kernel<<<grid, 256>>>(
            (const __nv_bfloat16*)xhi, (const __nv_bfloat16*)xlo,
            (const __nv_bfloat16*)whq, (const __nv_bfloat16*)wlq,
            qkv_b, (float*)qkv_p, QKVCOLS, DIMC, QSCALE);
    }
    // K2a: bias GEMM
    {
        dim3 grid(NHEAD * NTOK, B_WIN / 128);
        bias_kernel<<<grid, 256>>>(q_rpe, k_rpe);
    }
    // K2b: attention
    {
        dim3 grid(NHEAD, B_WIN);
        attn2_kernel<<<grid, 256>>>(mask, attn);
    }
    // K3: output projection (HMMA)
    {
        dim3 grid(DIMC / 64, TOKENS / 128);
        mma_gemm_kernel<<<grid, 256>>>(
            (const __nv_bfloat16*)ohi, (const __nv_bfloat16*)olo,
            (const __nv_bfloat16*)whp, (const __nv_bfloat16*)wlp,
            proj_b, out, DIMC, 0, 1.0f);
    }
}

// round 7
// speedup vs baseline: 1.6147x; 1.0830x over previous
#include <cuda_runtime.h>
#include <cuda_bf16.h>
#include <cstdint>

// ---------------------------------------------------------------------------
// WindowAttentionConvRpe: B=4096 windows, N=49, DIM=192, NH=6, HD=32, T=169.
//   K0 : split weights (transposed [N][K]) and x into bf16 hi/lo
//   K1 : QKV = X @ qkv_w + qkv_b          (HMMA bf16 3-term split, ldmatrix)
//   K2a: BIAS = [q;k] . gathered-RPE GEMM + additive window mask (SIMT)
//   K2b: attention (fp32 softmax), obuf written as bf16 hi/lo
//   K3 : OUT = O @ proj_w + proj_b        (HMMA)
// tcgen05 unavailable (PTX target sm_103 w/o 'a'); mma.sync path instead.
// ---------------------------------------------------------------------------

#define B_WIN   4096
#define NTOK    49
#define DIMC    192
#define NHEAD   6
#define HDIM    32
#define TSZ     169
#define TOKENS  (B_WIN * NTOK)
#define QKVCOLS (3 * DIMC)
#define QSCALE  0.17677669529663687f

__device__ float g_qkv [(size_t)TOKENS * QKVCOLS];
__device__ float g_bias[(size_t)B_WIN * NHEAD * NTOK * NTOK];
__device__ __nv_bfloat16 g_x_hi [(size_t)TOKENS * DIMC];
__device__ __nv_bfloat16 g_x_lo [(size_t)TOKENS * DIMC];
__device__ __nv_bfloat16 g_obuf_hi[(size_t)TOKENS * DIMC];
__device__ __nv_bfloat16 g_obuf_lo[(size_t)TOKENS * DIMC];
__device__ __nv_bfloat16 g_wqkv_hi[QKVCOLS * DIMC];   // [576][192] transposed
__device__ __nv_bfloat16 g_wqkv_lo[QKVCOLS * DIMC];
__device__ __nv_bfloat16 g_wproj_hi[DIMC * DIMC];     // [192][192] transposed
__device__ __nv_bfloat16 g_wproj_lo[DIMC * DIMC];

// ======================= K0a: weight transpose + split =====================
__global__ void splitw_kernel(const float* __restrict__ w,
                              __nv_bfloat16* __restrict__ thi,
                              __nv_bfloat16* __restrict__ tlo, int K, int N)
{
    int i = blockIdx.x * 256 + threadIdx.x;
    if (i >= K * N) return;
    int n = i / K, k = i % K;
    float v = w[(size_t)k * N + n];
    __nv_bfloat16 h = __float2bfloat16(v);
    thi[i] = h;
    tlo[i] = __float2bfloat16(v - __bfloat162float(h));
}

// ======================= K0b: activation split =============================
__global__ void splitf_kernel(const float* __restrict__ src,
                              __nv_bfloat16* __restrict__ hi,
                              __nv_bfloat16* __restrict__ lo, int n4)
{
    int i = blockIdx.x * 256 + threadIdx.x;
    if (i >= n4) return;
    float4 v = ((const float4*)src)[i];
    float vv[4] = {v.x, v.y, v.z, v.w};
    union { uint2 q; __nv_bfloat16 h[4]; } H, L;
    #pragma unroll
    for (int e = 0; e < 4; e++) {
        H.h[e] = __float2bfloat16(vv[e]);
        L.h[e] = __float2bfloat16(vv[e] - __bfloat162float(H.h[e]));
    }
    ((uint2*)hi)[i] = H.q;
    ((uint2*)lo)[i] = L.q;
}

// ======================= mma / ldmatrix helpers ============================
__device__ __forceinline__ void mma_bf16(float* d, const uint32_t* a,
                                         const uint32_t* b)
{
    asm volatile(
        "mma.sync.aligned.m16n8k16.row.col.f32.bf16.bf16.f32 "
        "{%0,%1,%2,%3}, {%4,%5,%6,%7}, {%8,%9}, {%0,%1,%2,%3};"
        : "+f"(d[0]), "+f"(d[1]), "+f"(d[2]), "+f"(d[3])
        : "r"(a[0]), "r"(a[1]), "r"(a[2]), "r"(a[3]),
          "r"(b[0]), "r"(b[1]));
}
__device__ __forceinline__ void ldsm_x4(uint32_t* r, uint32_t saddr)
{
    asm volatile("ldmatrix.sync.aligned.m8n8.x4.shared.b16 {%0,%1,%2,%3}, [%4];"
        : "=r"(r[0]), "=r"(r[1]), "=r"(r[2]), "=r"(r[3]) : "r"(saddr));
}
__device__ __forceinline__ uint32_t smem_u32(const void* p) {
    uint32_t a;
    asm("{ .reg .u64 t; cvta.to.shared.u64 t, %1; cvt.u32.u64 %0, t; }"
        : "=r"(a) : "l"(p));
    return a;
}

// ======================= K1/K3: HMMA split GEMM (smem + ldmatrix) ==========
#define APAD 40
__global__ __launch_bounds__(256) void mma_gemm_kernel(
    const __nv_bfloat16* __restrict__ Ahi, const __nv_bfloat16* __restrict__ Alo,
    const __nv_bfloat16* __restrict__ Bhi, const __nv_bfloat16* __restrict__ Blo,
    const float* __restrict__ bias, float* __restrict__ C,
    int Nld, int scale_limit, float scale)
{
    __shared__ __align__(16) __nv_bfloat16 sAh[128 * APAD];
    __shared__ __align__(16) __nv_bfloat16 sAl[128 * APAD];
    __shared__ __align__(16) __nv_bfloat16 sBh[64 * APAD];
    __shared__ __align__(16) __nv_bfloat16 sBl[64 * APAD];

    const int tid  = threadIdx.x;
    const int lane = tid & 31;
    const int wid  = tid >> 5;
    const int warpM = wid & 3;
    const int warpN = wid >> 2;
    const int g   = lane >> 2;
    const int tig = lane & 3;
    const int m0 = blockIdx.y * 128;
    const int n0 = blockIdx.x * 64;

    float acc[2][4][4];
    #pragma unroll
    for (int mt = 0; mt < 2; mt++)
        #pragma unroll
        for (int nt = 0; nt < 4; nt++)
            #pragma unroll
            for (int e = 0; e < 4; e++) acc[mt][nt][e] = 0.0f;

    const int rofA = ((lane >> 3) & 1) * 8 + (lane & 7);
    const int kofA = ((lane >> 4) & 1) * 8;
    const int rofB = ((lane >> 4) & 1) * 8 + (lane & 7);
    const int kofB = ((lane >> 3) & 1) * 8;

    const uint32_t aHiB = smem_u32(sAh) + ((warpM * 32 + rofA) * APAD + kofA) * 2;
    const uint32_t aLoB = smem_u32(sAl) + ((warpM * 32 + rofA) * APAD + kofA) * 2;
    const uint32_t bHiB = smem_u32(sBh) + ((warpN * 32 + rofB) * APAD + kofB) * 2;
    const uint32_t bLoB = smem_u32(sBl) + ((warpN * 32 + rofB) * APAD + kofB) * 2;

    for (int k0 = 0; k0 < 192; k0 += 32) {
        #pragma unroll
        for (int r = 0; r < 2; r++) {
            int c = tid + r * 256;
            int row = c >> 2, u = c & 3;
            size_t src = (size_t)(m0 + row) * 192 + k0 + u * 8;
            *(uint4*)(sAh + row * APAD + u * 8) = *(const uint4*)(Ahi + src);
            *(uint4*)(sAl + row * APAD + u * 8) = *(const uint4*)(Alo + src);
        }
        {
            int row = tid >> 2, u = tid & 3;
            size_t src = (size_t)(n0 + row) * 192 + k0 + u * 8;
            *(uint4*)(sBh + row * APAD + u * 8) = *(const uint4*)(Bhi + src);
            *(uint4*)(sBl + row * APAD + u * 8) = *(const uint4*)(Blo + src);
        }
        __syncthreads();

        #pragma unroll
        for (int s = 0; s < 2; s++) {
            uint32_t ahi[2][4], alo[2][4], bhi[2][4], blo[2][4];
            #pragma unroll
            for (int mt = 0; mt < 2; mt++) {
                uint32_t off = (uint32_t)((mt * 16 * APAD + s * 16) * 2);
                ldsm_x4(ahi[mt], aHiB + off);
                ldsm_x4(alo[mt], aLoB + off);
            }
            #pragma unroll
            for (int p = 0; p < 2; p++) {
                uint32_t off = (uint32_t)((p * 16 * APAD + s * 16) * 2);
                ldsm_x4(bhi[p], bHiB + off);
                ldsm_x4(blo[p], bLoB + off);
            }
            #pragma unroll
            for (int mt = 0; mt < 2; mt++)
                #pragma unroll
                for (int nt = 0; nt < 4; nt++) {
                    const uint32_t* bh = &bhi[nt >> 1][(nt & 1) * 2];
                    const uint32_t* bl = &blo[nt >> 1][(nt & 1) * 2];
                    mma_bf16(acc[mt][nt], ahi[mt], bh);
                    mma_bf16(acc[mt][nt], ahi[mt], bl);
                    mma_bf16(acc[mt][nt], alo[mt], bh);
                }
        }
        __syncthreads();
    }

    #pragma unroll
    for (int mt = 0; mt < 2; mt++) {
        int row = m0 + warpM * 32 + mt * 16 + g;
        #pragma unroll
        for (int nt = 0; nt < 4; nt++) {
            int col = n0 + warpN * 32 + nt * 8 + 2 * tig;
            float b0 = bias[col], b1 = bias[col + 1];
            float c0 = acc[mt][nt][0] + b0;
            float c1 = acc[mt][nt][1] + b1;
            float c2 = acc[mt][nt][2] + b0;
            float c3 = acc[mt][nt][3] + b1;
            if (col < scale_limit) {
                c0 *= scale; c1 *= scale; c2 *= scale; c3 *= scale;
            }
            *(float2*)(C + (size_t)row * Nld + col)       = make_float2(c0, c1);
            *(float2*)(C + (size_t)(row + 8) * Nld + col) = make_float2(c2, c3);
        }
    }
}

// ======================= K2a: bias GEMM + mask fuse (SIMT) =================
__global__ __launch_bounds__(256) void bias_kernel(
    const float* __restrict__ q_rpe, const float* __restrict__ k_rpe,
    const float* __restrict__ mask)
{
    __shared__ float A_s[64][128];
    __shared__ float G_s[64][64];

    const int hi = blockIdx.x;
    const int h  = hi / NTOK;
    const int i  = hi % NTOK;
    const int ri = i / 7, ci = i % 7;
    const int m0 = blockIdx.y * 128;
    const int tid = threadIdx.x;

    for (int f = tid; f < 8 * 128; f += 256) {
        int bl = f & 127;
        int g4 = f >> 7;
        size_t row = ((size_t)(m0 + bl) * NTOK + i) * QKVCOLS + h * HDIM;
        float4 qv = *(const float4*)(g_qkv + row + g4 * 4);
        A_s[g4 * 4 + 0][bl] = qv.x; A_s[g4 * 4 + 1][bl] = qv.y;
        A_s[g4 * 4 + 2][bl] = qv.z; A_s[g4 * 4 + 3][bl] = qv.w;
        float4 kv = *(const float4*)(g_qkv + row + DIMC + g4 * 4);
        A_s[32 + g4 * 4 + 0][bl] = kv.x; A_s[32 + g4 * 4 + 1][bl] = kv.y;
        A_s[32 + g4 * 4 + 2][bl] = kv.z; A_s[32 + g4 * 4 + 3][bl] = kv.w;
    }
    for (int f = tid; f < 64 * 64; f += 256) {
        int d = f >> 6, j = f & 63;
        float val = 0.0f;
        if (j < NTOK) {
            int t = (ri - j / 7 + 6) * 13 + (ci - j % 7 + 6);
            val = (d < HDIM) ? q_rpe[(h * HDIM + d) * TSZ + t]
                             : k_rpe[(h * HDIM + (d - 32)) * TSZ + t];
        }
        G_s[d][j] = val;
    }
    __syncthreads();

    const int tx = tid & 7;
    const int ty = tid >> 3;

    float acc[4][8];
    #pragma unroll
    for (int r = 0; r < 4; r++)
        #pragma unroll
        for (int c = 0; c < 8; c++) acc[r][c] = 0.0f;

    #pragma unroll 16
    for (int d = 0; d < 64; d++) {
        float4 a4 = *(float4*)&A_s[d][ty * 4];
        float4 g0 = *(float4*)&G_s[d][tx * 8];
        float4 g1 = *(float4*)&G_s[d][tx * 8 + 4];
        float a[4] = {a4.x, a4.y, a4.z, a4.w};
        float g[8] = {g0.x, g0.y, g0.z, g0.w, g1.x, g1.y, g1.z, g1.w};
        #pragma unroll
        for (int r = 0; r < 4; r++)
            #pragma unroll
            for (int c = 0; c < 8; c++)
                acc[r][c] += a[r] * g[c];
    }

    #pragma unroll
    for (int r = 0; r < 4; r++) {
        int bw = m0 + ty * 4 + r;
        size_t base = (((size_t)bw * NHEAD + h) * NTOK + i) * NTOK;
        const float* mrow = mask + ((size_t)(bw & 63) * NTOK + i) * NTOK;
        #pragma unroll
        for (int c = 0; c < 8; c++) {
            int j = tx * 8 + c;
            if (j < NTOK) g_bias[base + j] = acc[r][c] + mrow[j];
        }
    }
}

// ======================= K2b: attention ====================================
// One (b,h) per block, 256 threads. K staged coalesced into smem transposed;
// lane-j1 K column cached in 32 regs; j2 half read from smem. Bias (incl.
// mask) prefetched for all of a warp's rows before the score loop.
#define KTP 52
__global__ __launch_bounds__(256) void attn2_kernel(float* __restrict__ attn_out)
{
    __shared__ float q_s[49 * 32];
    __shared__ float v_s[49 * 32];
    __shared__ float kT_s[32 * KTP];
    __shared__ float p_s[49 * 52];

    const int h = blockIdx.x;
    const int b = blockIdx.y;
    const int tid  = threadIdx.x;
    const int lane = tid & 31;
    const int warp = tid >> 5;

    // stage q, v, k (all coalesced float4; k transposed into kT_s[d][j])
    for (int f = tid; f < 49 * 8; f += 256) {
        int i = f >> 3, c4 = (f & 7) * 4;
        size_t row = ((size_t)b * NTOK + i) * QKVCOLS + h * HDIM;
        *(float4*)(q_s + i * 32 + c4) = *(const float4*)(g_qkv + row + c4);
        *(float4*)(v_s + i * 32 + c4) = *(const float4*)(g_qkv + row + 2 * DIMC + c4);
        float4 kv = *(const float4*)(g_qkv + row + DIMC + c4);
        kT_s[(c4 + 0) * KTP + i] = kv.x;
        kT_s[(c4 + 1) * KTP + i] = kv.y;
        kT_s[(c4 + 2) * KTP + i] = kv.z;
        kT_s[(c4 + 3) * KTP + i] = kv.w;
    }
    __syncthreads();

    const float* brow0 = g_bias + ((size_t)b * NHEAD + h) * (49 * 49);
    float* attn_b = attn_out + ((size_t)b * NHEAD + h) * (49 * 49);
    const bool has2 = (lane < 17);
    const int j1 = lane;
    const int j2 = lane + 32;
    const int j2c = min(j2, 48);
    const int nrows = (warp == 0) ? 7 : 6;

    // prefetch bias(+mask) for all rows (MLP-batched LDG)
    float bm1[7], bm2[7];
    #pragma unroll 7
    for (int r = 0; r < nrows; r++) {
        int i = warp + r * 8;
        bm1[r] = brow0[i * 49 + j1];
        bm2[r] = has2 ? brow0[i * 49 + j2] : 0.0f;
    }

    // lane's j1 key column into registers (conflict-free LDS)
    float kr1[32];
    #pragma unroll
    for (int d = 0; d < 32; d++) kr1[d] = kT_s[d * KTP + j1];

    #pragma unroll 1
    for (int r = 0; r < nrows; r++) {
        const int i = warp + r * 8;
        float acc1 = 0.0f, acc2 = 0.0f;
        #pragma unroll
        for (int c = 0; c < 8; c++) {
            float4 q4 = *(const float4*)(q_s + i * 32 + c * 4);
            float qq[4] = {q4.x, q4.y, q4.z, q4.w};
            #pragma unroll
            for (int e = 0; e < 4; e++) {
                int d = c * 4 + e;
                acc1 += qq[e] * kr1[d];
                acc2 += qq[e] * kT_s[d * KTP + j2c];
            }
        }
        acc1 += bm1[r];
        acc2 += bm2[r];

        float mx = has2 ? fmaxf(acc1, acc2) : acc1;
        #pragma unroll
        for (int o = 16; o > 0; o >>= 1)
            mx = fmaxf(mx, __shfl_xor_sync(0xffffffffu, mx, o));
        float e1 = __expf(acc1 - mx);
        float e2 = has2 ? __expf(acc2 - mx) : 0.0f;
        float sum = e1 + e2;
        #pragma unroll
        for (int o = 16; o > 0; o >>= 1)
            sum += __shfl_xor_sync(0xffffffffu, sum, o);
        float inv = 1.0f / sum;
        float p1 = e1 * inv, p2 = e2 * inv;

        p_s[i * 52 + j1]    = p1;
        attn_b[i * 49 + j1] = p1;
        if (has2) { p_s[i * 52 + j2] = p2; attn_b[i * 49 + j2] = p2; }
    }
    __syncwarp();

    float o[7];
    #pragma unroll
    for (int r = 0; r < 7; r++) o[r] = 0.0f;

    #pragma unroll 1
    for (int j4 = 0; j4 < 12; j4++) {
        float v0 = v_s[(j4 * 4 + 0) * 32 + lane];
        float v1 = v_s[(j4 * 4 + 1) * 32 + lane];
        float v2 = v_s[(j4 * 4 + 2) * 32 + lane];
        float v3 = v_s[(j4 * 4 + 3) * 32 + lane];
        for (int r = 0; r < nrows; r++) {
            float4 p4 = *(const float4*)&p_s[(warp + r * 8) * 52 + j4 * 4];
            o[r] += p4.x * v0 + p4.y * v1 + p4.z * v2 + p4.w * v3;
        }
    }
    {
        float v48 = v_s[48 * 32 + lane];
        for (int r = 0; r < nrows; r++)
            o[r] += p_s[(warp + r * 8) * 52 + 48] * v48;
    }
    for (int r = 0; r < nrows; r++) {
        int i = warp + r * 8;
        size_t idx = ((size_t)b * NTOK + i) * DIMC + h * HDIM + lane;
        float ov = o[r];
        __nv_bfloat16 hi = __float2bfloat16(ov);
        g_obuf_hi[idx] = hi;
        g_obuf_lo[idx] = __float2bfloat16(ov - __bfloat162float(hi));
    }
}

// ---------------------------------------------------------------------------
extern "C" void kernel_launch(void* const* d_in, const int* in_sizes, int n_in,
                              void* d_out, int out_size)
{
    const float* x      = (const float*)d_in[0];
    const float* mask   = (const float*)d_in[1];
    const float* qkv_w  = (const float*)d_in[2];
    const float* qkv_b  = (const float*)d_in[3];
    const float* q_rpe  = (const float*)d_in[4];
    const float* k_rpe  = (const float*)d_in[5];
    const float* proj_w = (const float*)d_in[6];
    const float* proj_b = (const float*)d_in[7];
    // d_in[8] = rpe_indices: recomputed analytically in-kernel

    float* out  = (float*)d_out;
    float* attn = out + (size_t)TOKENS * DIMC;

    void *qkv_p, *xhi, *xlo, *whq, *wlq, *whp, *wlp, *ohi, *olo;
    cudaGetSymbolAddress(&qkv_p, g_qkv);
    cudaGetSymbolAddress(&xhi, g_x_hi);
    cudaGetSymbolAddress(&xlo, g_x_lo);
    cudaGetSymbolAddress(&whq, g_wqkv_hi);
    cudaGetSymbolAddress(&wlq, g_wqkv_lo);
    cudaGetSymbolAddress(&whp, g_wproj_hi);
    cudaGetSymbolAddress(&wlp, g_wproj_lo);
    cudaGetSymbolAddress(&ohi, g_obuf_hi);
    cudaGetSymbolAddress(&olo, g_obuf_lo);

    // K0: splits
    splitw_kernel<<<(DIMC * QKVCOLS + 255) / 256, 256>>>(
        qkv_w, (__nv_bfloat16*)whq, (__nv_bfloat16*)wlq, DIMC, QKVCOLS);
    splitw_kernel<<<(DIMC * DIMC + 255) / 256, 256>>>(
        proj_w, (__nv_bfloat16*)whp, (__nv_bfloat16*)wlp, DIMC, DIMC);
    {
        int n4 = TOKENS * DIMC / 4;
        splitf_kernel<<<(n4 + 255) / 256, 256>>>(
            x, (__nv_bfloat16*)xhi, (__nv_bfloat16*)xlo, n4);
    }

    // K1: QKV projection (HMMA) — q cols pre-scaled
    {
        dim3 grid(QKVCOLS / 64, TOKENS / 128);
        mma_gemm_kernel<<<grid, 256>>>(
            (const __nv_bfloat16*)xhi, (const __nv_bfloat16*)xlo,
            (const __nv_bfloat16*)whq, (const __nv_bfloat16*)wlq,
            qkv_b, (float*)qkv_p, QKVCOLS, DIMC, QSCALE);
    }
    // K2a: bias GEMM (+mask)
    {
        dim3 grid(NHEAD * NTOK, B_WIN / 128);
        bias_kernel<<<grid, 256>>>(q_rpe, k_rpe, mask);
    }
    // K2b: attention
    {
        dim3 grid(NHEAD, B_WIN);
        attn2_kernel<<<grid, 256>>>(attn);
    }
    // K3: output projection (HMMA)
    {
        dim3 grid(DIMC / 64, TOKENS / 128);
        mma_gemm_kernel<<<grid, 256>>>(
            (const __nv_bfloat16*)ohi, (const __nv_bfloat16*)olo,
            (const __nv_bfloat16*)whp, (const __nv_bfloat16*)wlp,
            proj_b, out, DIMC, 0, 1.0f);
    }
}

// round 8
// speedup vs baseline: 1.8125x; 1.1226x over previous
#include <cuda_runtime.h>
#include <cuda_bf16.h>
#include <cstdint>

// ---------------------------------------------------------------------------
// WindowAttentionConvRpe: B=4096 windows, N=49, DIM=192, NH=6, HD=32, T=169.
//   K0 : split weights (transposed [N][K]) and x into bf16 hi/lo
//   K1 : QKV = X @ qkv_w + qkv_b          (HMMA bf16 3-term split, ldmatrix)
//   K2a: BIAS = [q;k] . gathered-RPE GEMM + additive window mask (SIMT)
//   K2b: attention, HMMA flash-style (QK^T and P.V on tensor pipe)
//   K3 : OUT = O @ proj_w + proj_b        (HMMA)
// tcgen05 unavailable (PTX target sm_103 w/o 'a'); mma.sync path instead.
// ---------------------------------------------------------------------------

#define B_WIN   4096
#define NTOK    49
#define DIMC    192
#define NHEAD   6
#define HDIM    32
#define TSZ     169
#define TOKENS  (B_WIN * NTOK)
#define QKVCOLS (3 * DIMC)
#define QSCALE  0.17677669529663687f

__device__ float g_qkv [(size_t)TOKENS * QKVCOLS];
__device__ float g_bias[(size_t)B_WIN * NHEAD * NTOK * NTOK];
__device__ __nv_bfloat16 g_x_hi [(size_t)TOKENS * DIMC];
__device__ __nv_bfloat16 g_x_lo [(size_t)TOKENS * DIMC];
__device__ __nv_bfloat16 g_obuf_hi[(size_t)TOKENS * DIMC];
__device__ __nv_bfloat16 g_obuf_lo[(size_t)TOKENS * DIMC];
__device__ __nv_bfloat16 g_wqkv_hi[QKVCOLS * DIMC];   // [576][192] transposed
__device__ __nv_bfloat16 g_wqkv_lo[QKVCOLS * DIMC];
__device__ __nv_bfloat16 g_wproj_hi[DIMC * DIMC];     // [192][192] transposed
__device__ __nv_bfloat16 g_wproj_lo[DIMC * DIMC];

// ======================= K0a: weight transpose + split =====================
__global__ void splitw_kernel(const float* __restrict__ w,
                              __nv_bfloat16* __restrict__ thi,
                              __nv_bfloat16* __restrict__ tlo, int K, int N)
{
    int i = blockIdx.x * 256 + threadIdx.x;
    if (i >= K * N) return;
    int n = i / K, k = i % K;
    float v = w[(size_t)k * N + n];
    __nv_bfloat16 h = __float2bfloat16(v);
    thi[i] = h;
    tlo[i] = __float2bfloat16(v - __bfloat162float(h));
}

// ======================= K0b: activation split =============================
__global__ void splitf_kernel(const float* __restrict__ src,
                              __nv_bfloat16* __restrict__ hi,
                              __nv_bfloat16* __restrict__ lo, int n4)
{
    int i = blockIdx.x * 256 + threadIdx.x;
    if (i >= n4) return;
    float4 v = ((const float4*)src)[i];
    float vv[4] = {v.x, v.y, v.z, v.w};
    union { uint2 q; __nv_bfloat16 h[4]; } H, L;
    #pragma unroll
    for (int e = 0; e < 4; e++) {
        H.h[e] = __float2bfloat16(vv[e]);
        L.h[e] = __float2bfloat16(vv[e] - __bfloat162float(H.h[e]));
    }
    ((uint2*)hi)[i] = H.q;
    ((uint2*)lo)[i] = L.q;
}

// ======================= mma / ldmatrix helpers ============================
__device__ __forceinline__ void mma_bf16(float* d, const uint32_t* a,
                                         const uint32_t* b)
{
    asm volatile(
        "mma.sync.aligned.m16n8k16.row.col.f32.bf16.bf16.f32 "
        "{%0,%1,%2,%3}, {%4,%5,%6,%7}, {%8,%9}, {%0,%1,%2,%3};"
        : "+f"(d[0]), "+f"(d[1]), "+f"(d[2]), "+f"(d[3])
        : "r"(a[0]), "r"(a[1]), "r"(a[2]), "r"(a[3]),
          "r"(b[0]), "r"(b[1]));
}
__device__ __forceinline__ void ldsm_x4(uint32_t* r, uint32_t saddr)
{
    asm volatile("ldmatrix.sync.aligned.m8n8.x4.shared.b16 {%0,%1,%2,%3}, [%4];"
        : "=r"(r[0]), "=r"(r[1]), "=r"(r[2]), "=r"(r[3]) : "r"(saddr));
}
__device__ __forceinline__ void ldsm_x4_t(uint32_t* r, uint32_t saddr)
{
    asm volatile("ldmatrix.sync.aligned.m8n8.x4.trans.shared.b16 {%0,%1,%2,%3}, [%4];"
        : "=r"(r[0]), "=r"(r[1]), "=r"(r[2]), "=r"(r[3]) : "r"(saddr));
}
__device__ __forceinline__ uint32_t smem_u32(const void* p) {
    uint32_t a;
    asm("{ .reg .u64 t; cvta.to.shared.u64 t, %1; cvt.u32.u64 %0, t; }"
        : "=r"(a) : "l"(p));
    return a;
}
// pack (a,b) into bf16x2 hi word, residual into lo word
__device__ __forceinline__ uint32_t pk_split(float a, float b, uint32_t& lo) {
    __nv_bfloat16 ha = __float2bfloat16(a), hb = __float2bfloat16(b);
    __nv_bfloat16 la = __float2bfloat16(a - __bfloat162float(ha));
    __nv_bfloat16 lb = __float2bfloat16(b - __bfloat162float(hb));
    __nv_bfloat162 H; H.x = ha; H.y = hb;
    __nv_bfloat162 L; L.x = la; L.y = lb;
    lo = *(uint32_t*)&L;
    return *(uint32_t*)&H;
}

// ======================= K1/K3: HMMA split GEMM (smem + ldmatrix) ==========
#define APAD 40
__global__ __launch_bounds__(256) void mma_gemm_kernel(
    const __nv_bfloat16* __restrict__ Ahi, const __nv_bfloat16* __restrict__ Alo,
    const __nv_bfloat16* __restrict__ Bhi, const __nv_bfloat16* __restrict__ Blo,
    const float* __restrict__ bias, float* __restrict__ C,
    int Nld, int scale_limit, float scale)
{
    __shared__ __align__(16) __nv_bfloat16 sAh[128 * APAD];
    __shared__ __align__(16) __nv_bfloat16 sAl[128 * APAD];
    __shared__ __align__(16) __nv_bfloat16 sBh[64 * APAD];
    __shared__ __align__(16) __nv_bfloat16 sBl[64 * APAD];

    const int tid  = threadIdx.x;
    const int lane = tid & 31;
    const int wid  = tid >> 5;
    const int warpM = wid & 3;
    const int warpN = wid >> 2;
    const int g   = lane >> 2;
    const int tig = lane & 3;
    const int m0 = blockIdx.y * 128;
    const int n0 = blockIdx.x * 64;

    float acc[2][4][4];
    #pragma unroll
    for (int mt = 0; mt < 2; mt++)
        #pragma unroll
        for (int nt = 0; nt < 4; nt++)
            #pragma unroll
            for (int e = 0; e < 4; e++) acc[mt][nt][e] = 0.0f;

    const int rofA = ((lane >> 3) & 1) * 8 + (lane & 7);
    const int kofA = ((lane >> 4) & 1) * 8;
    const int rofB = ((lane >> 4) & 1) * 8 + (lane & 7);
    const int kofB = ((lane >> 3) & 1) * 8;

    const uint32_t aHiB = smem_u32(sAh) + ((warpM * 32 + rofA) * APAD + kofA) * 2;
    const uint32_t aLoB = smem_u32(sAl) + ((warpM * 32 + rofA) * APAD + kofA) * 2;
    const uint32_t bHiB = smem_u32(sBh) + ((warpN * 32 + rofB) * APAD + kofB) * 2;
    const uint32_t bLoB = smem_u32(sBl) + ((warpN * 32 + rofB) * APAD + kofB) * 2;

    for (int k0 = 0; k0 < 192; k0 += 32) {
        #pragma unroll
        for (int r = 0; r < 2; r++) {
            int c = tid + r * 256;
            int row = c >> 2, u = c & 3;
            size_t src = (size_t)(m0 + row) * 192 + k0 + u * 8;
            *(uint4*)(sAh + row * APAD + u * 8) = *(const uint4*)(Ahi + src);
            *(uint4*)(sAl + row * APAD + u * 8) = *(const uint4*)(Alo + src);
        }
        {
            int row = tid >> 2, u = tid & 3;
            size_t src = (size_t)(n0 + row) * 192 + k0 + u * 8;
            *(uint4*)(sBh + row * APAD + u * 8) = *(const uint4*)(Bhi + src);
            *(uint4*)(sBl + row * APAD + u * 8) = *(const uint4*)(Blo + src);
        }
        __syncthreads();

        #pragma unroll
        for (int s = 0; s < 2; s++) {
            uint32_t ahi[2][4], alo[2][4], bhi[2][4], blo[2][4];
            #pragma unroll
            for (int mt = 0; mt < 2; mt++) {
                uint32_t off = (uint32_t)((mt * 16 * APAD + s * 16) * 2);
                ldsm_x4(ahi[mt], aHiB + off);
                ldsm_x4(alo[mt], aLoB + off);
            }
            #pragma unroll
            for (int p = 0; p < 2; p++) {
                uint32_t off = (uint32_t)((p * 16 * APAD + s * 16) * 2);
                ldsm_x4(bhi[p], bHiB + off);
                ldsm_x4(blo[p], bLoB + off);
            }
            #pragma unroll
            for (int mt = 0; mt < 2; mt++)
                #pragma unroll
                for (int nt = 0; nt < 4; nt++) {
                    const uint32_t* bh = &bhi[nt >> 1][(nt & 1) * 2];
                    const uint32_t* bl = &blo[nt >> 1][(nt & 1) * 2];
                    mma_bf16(acc[mt][nt], ahi[mt], bh);
                    mma_bf16(acc[mt][nt], ahi[mt], bl);
                    mma_bf16(acc[mt][nt], alo[mt], bh);
                }
        }
        __syncthreads();
    }

    #pragma unroll
    for (int mt = 0; mt < 2; mt++) {
        int row = m0 + warpM * 32 + mt * 16 + g;
        #pragma unroll
        for (int nt = 0; nt < 4; nt++) {
            int col = n0 + warpN * 32 + nt * 8 + 2 * tig;
            float b0 = bias[col], b1 = bias[col + 1];
            float c0 = acc[mt][nt][0] + b0;
            float c1 = acc[mt][nt][1] + b1;
            float c2 = acc[mt][nt][2] + b0;
            float c3 = acc[mt][nt][3] + b1;
            if (col < scale_limit) {
                c0 *= scale; c1 *= scale; c2 *= scale; c3 *= scale;
            }
            *(float2*)(C + (size_t)row * Nld + col)       = make_float2(c0, c1);
            *(float2*)(C + (size_t)(row + 8) * Nld + col) = make_float2(c2, c3);
        }
    }
}

// ======================= K2a: bias GEMM + mask fuse (SIMT) =================
__global__ __launch_bounds__(256) void bias_kernel(
    const float* __restrict__ q_rpe, const float* __restrict__ k_rpe,
    const float* __restrict__ mask)
{
    __shared__ float A_s[64][128];
    __shared__ float G_s[64][64];

    const int hi = blockIdx.x;
    const int h  = hi / NTOK;
    const int i  = hi % NTOK;
    const int ri = i / 7, ci = i % 7;
    const int m0 = blockIdx.y * 128;
    const int tid = threadIdx.x;

    for (int f = tid; f < 8 * 128; f += 256) {
        int bl = f & 127;
        int g4 = f >> 7;
        size_t row = ((size_t)(m0 + bl) * NTOK + i) * QKVCOLS + h * HDIM;
        float4 qv = *(const float4*)(g_qkv + row + g4 * 4);
        A_s[g4 * 4 + 0][bl] = qv.x; A_s[g4 * 4 + 1][bl] = qv.y;
        A_s[g4 * 4 + 2][bl] = qv.z; A_s[g4 * 4 + 3][bl] = qv.w;
        float4 kv = *(const float4*)(g_qkv + row + DIMC + g4 * 4);
        A_s[32 + g4 * 4 + 0][bl] = kv.x; A_s[32 + g4 * 4 + 1][bl] = kv.y;
        A_s[32 + g4 * 4 + 2][bl] = kv.z; A_s[32 + g4 * 4 + 3][bl] = kv.w;
    }
    for (int f = tid; f < 64 * 64; f += 256) {
        int d = f >> 6, j = f & 63;
        float val = 0.0f;
        if (j < NTOK) {
            int t = (ri - j / 7 + 6) * 13 + (ci - j % 7 + 6);
            val = (d < HDIM) ? q_rpe[(h * HDIM + d) * TSZ + t]
                             : k_rpe[(h * HDIM + (d - 32)) * TSZ + t];
        }
        G_s[d][j] = val;
    }
    __syncthreads();

    const int tx = tid & 7;
    const int ty = tid >> 3;

    float acc[4][8];
    #pragma unroll
    for (int r = 0; r < 4; r++)
        #pragma unroll
        for (int c = 0; c < 8; c++) acc[r][c] = 0.0f;

    #pragma unroll 16
    for (int d = 0; d < 64; d++) {
        float4 a4 = *(float4*)&A_s[d][ty * 4];
        float4 g0 = *(float4*)&G_s[d][tx * 8];
        float4 g1 = *(float4*)&G_s[d][tx * 8 + 4];
        float a[4] = {a4.x, a4.y, a4.z, a4.w};
        float g[8] = {g0.x, g0.y, g0.z, g0.w, g1.x, g1.y, g1.z, g1.w};
        #pragma unroll
        for (int r = 0; r < 4; r++)
            #pragma unroll
            for (int c = 0; c < 8; c++)
                acc[r][c] += a[r] * g[c];
    }

    #pragma unroll
    for (int r = 0; r < 4; r++) {
        int bw = m0 + ty * 4 + r;
        size_t base = (((size_t)bw * NHEAD + h) * NTOK + i) * NTOK;
        const float* mrow = mask + ((size_t)(bw & 63) * NTOK + i) * NTOK;
        #pragma unroll
        for (int c = 0; c < 8; c++) {
            int j = tx * 8 + c;
            if (j < NTOK) g_bias[base + j] = acc[r][c] + mrow[j];
        }
    }
}

// ======================= K2b: attention (HMMA flash-style) =================
// One (b,h) per block, 128 threads (4 warps, 16 rows each).
// S = Q@K^T (bf16 3-term), +bias(+mask) from smem, softmax in regs,
// O = P@V with P accumulator regs re-used as A-fragments (hi/lo split).
#define QP 40
__global__ __launch_bounds__(128) void attn3_kernel(float* __restrict__ attn_out)
{
    __shared__ __align__(16) __nv_bfloat16 qh[64 * QP], ql[64 * QP];
    __shared__ __align__(16) __nv_bfloat16 kh[64 * QP], kl[64 * QP];
    __shared__ __align__(16) __nv_bfloat16 vh[64 * QP], vl[64 * QP];
    __shared__ float bias_s[49 * 52];

    const int h = blockIdx.x;
    const int b = blockIdx.y;
    const int tid  = threadIdx.x;
    const int lane = tid & 31;
    const int warp = tid >> 5;
    const int g   = lane >> 2;
    const int tig = lane & 3;

    // ---- stage q,k,v as bf16 hi/lo (rows 49-63 zeroed) ----
    for (int f = tid; f < 64 * 8; f += 128) {
        int i = f >> 3, c4 = (f & 7) * 4;
        float4 qv = {0,0,0,0}, kv = {0,0,0,0}, vv = {0,0,0,0};
        if (i < NTOK) {
            size_t row = ((size_t)b * NTOK + i) * QKVCOLS + h * HDIM;
            qv = *(const float4*)(g_qkv + row + c4);
            kv = *(const float4*)(g_qkv + row + DIMC + c4);
            vv = *(const float4*)(g_qkv + row + 2 * DIMC + c4);
        }
        float qa[4] = {qv.x, qv.y, qv.z, qv.w};
        float ka[4] = {kv.x, kv.y, kv.z, kv.w};
        float va[4] = {vv.x, vv.y, vv.z, vv.w};
        union { uint2 u; __nv_bfloat16 e[4]; } QH, QL, KH, KL, VH, VL;
        #pragma unroll
        for (int e = 0; e < 4; e++) {
            QH.e[e] = __float2bfloat16(qa[e]);
            QL.e[e] = __float2bfloat16(qa[e] - __bfloat162float(QH.e[e]));
            KH.e[e] = __float2bfloat16(ka[e]);
            KL.e[e] = __float2bfloat16(ka[e] - __bfloat162float(KH.e[e]));
            VH.e[e] = __float2bfloat16(va[e]);
            VL.e[e] = __float2bfloat16(va[e] - __bfloat162float(VH.e[e]));
        }
        int o = i * QP + c4;
        *(uint2*)(qh + o) = QH.u; *(uint2*)(ql + o) = QL.u;
        *(uint2*)(kh + o) = KH.u; *(uint2*)(kl + o) = KL.u;
        *(uint2*)(vh + o) = VH.u; *(uint2*)(vl + o) = VL.u;
    }
    // ---- stage bias(+mask) ----
    {
        const float* brow0 = g_bias + ((size_t)b * NHEAD + h) * (NTOK * NTOK);
        for (int f = tid; f < NTOK * NTOK; f += 128) {
            int r = f / 49, c = f - r * 49;
            bias_s[r * 52 + c] = brow0[f];
        }
    }
    __syncthreads();

    const int m0 = warp * 16;
    const int i1 = m0 + g;
    const int i2 = m0 + g + 8;

    // ldmatrix lane offsets (validated in gemm kernel)
    const int rofA = ((lane >> 3) & 1) * 8 + (lane & 7);
    const int kofA = ((lane >> 4) & 1) * 8;
    const int rofB = ((lane >> 4) & 1) * 8 + (lane & 7);
    const int kofB = ((lane >> 3) & 1) * 8;
    const int rofV = ((lane >> 3) & 1) * 8 + (lane & 7);
    const int cofV = ((lane >> 4) & 1) * 8;

    // ---- S = Q @ K^T ----
    uint32_t aQh[2][4], aQl[2][4];
    {
        uint32_t qb = smem_u32(qh) + ((m0 + rofA) * QP + kofA) * 2;
        uint32_t lb = smem_u32(ql) + ((m0 + rofA) * QP + kofA) * 2;
        #pragma unroll
        for (int s = 0; s < 2; s++) {
            ldsm_x4(aQh[s], qb + s * 32);
            ldsm_x4(aQl[s], lb + s * 32);
        }
    }
    float sv[8][4];
    #pragma unroll
    for (int nt = 0; nt < 8; nt++)
        #pragma unroll
        for (int e = 0; e < 4; e++) sv[nt][e] = 0.0f;

    {
        uint32_t kb = smem_u32(kh) + (rofB * QP + kofB) * 2;
        uint32_t lb = smem_u32(kl) + (rofB * QP + kofB) * 2;
        #pragma unroll
        for (int p = 0; p < 4; p++) {
            uint32_t kH[2][4], kL[2][4];
            #pragma unroll
            for (int s = 0; s < 2; s++) {
                uint32_t off = (uint32_t)((p * 16 * QP + s * 16) * 2);
                ldsm_x4(kH[s], kb + off);
                ldsm_x4(kL[s], lb + off);
            }
            #pragma unroll
            for (int half = 0; half < 2; half++) {
                int nt = 2 * p + half;
                #pragma unroll
                for (int s = 0; s < 2; s++) {
                    mma_bf16(sv[nt], aQh[s], &kH[s][half * 2]);
                    mma_bf16(sv[nt], aQh[s], &kL[s][half * 2]);
                    mma_bf16(sv[nt], aQl[s], &kH[s][half * 2]);
                }
            }
        }
    }

    // ---- bias + mask + softmax (rows i1, i2 in regs) ----
    float mx1 = -3.0e38f, mx2 = -3.0e38f;
    #pragma unroll
    for (int nt = 0; nt < 8; nt++) {
        int col0 = nt * 8 + 2 * tig;
        int col1 = col0 + 1;
        float b00 = (i1 < NTOK && col0 < NTOK) ? bias_s[i1 * 52 + col0] : 0.0f;
        float b01 = (i1 < NTOK && col1 < NTOK) ? bias_s[i1 * 52 + col1] : 0.0f;
        float b10 = (i2 < NTOK && col0 < NTOK) ? bias_s[i2 * 52 + col0] : 0.0f;
        float b11 = (i2 < NTOK && col1 < NTOK) ? bias_s[i2 * 52 + col1] : 0.0f;
        float v0 = sv[nt][0] + b00; if (col0 >= NTOK) v0 = -1.0e30f;
        float v1 = sv[nt][1] + b01; if (col1 >= NTOK) v1 = -1.0e30f;
        float v2 = sv[nt][2] + b10; if (col0 >= NTOK) v2 = -1.0e30f;
        float v3 = sv[nt][3] + b11; if (col1 >= NTOK) v3 = -1.0e30f;
        sv[nt][0] = v0; sv[nt][1] = v1; sv[nt][2] = v2; sv[nt][3] = v3;
        mx1 = fmaxf(mx1, fmaxf(v0, v1));
        mx2 = fmaxf(mx2, fmaxf(v2, v3));
    }
    mx1 = fmaxf(mx1, __shfl_xor_sync(0xffffffffu, mx1, 1));
    mx1 = fmaxf(mx1, __shfl_xor_sync(0xffffffffu, mx1, 2));
    mx2 = fmaxf(mx2, __shfl_xor_sync(0xffffffffu, mx2, 1));
    mx2 = fmaxf(mx2, __shfl_xor_sync(0xffffffffu, mx2, 2));

    float sum1 = 0.0f, sum2 = 0.0f;
    #pragma unroll
    for (int nt = 0; nt < 8; nt++) {
        float e0 = __expf(sv[nt][0] - mx1);
        float e1 = __expf(sv[nt][1] - mx1);
        float e2 = __expf(sv[nt][2] - mx2);
        float e3 = __expf(sv[nt][3] - mx2);
        sv[nt][0] = e0; sv[nt][1] = e1; sv[nt][2] = e2; sv[nt][3] = e3;
        sum1 += e0 + e1;
        sum2 += e2 + e3;
    }
    sum1 += __shfl_xor_sync(0xffffffffu, sum1, 1);
    sum1 += __shfl_xor_sync(0xffffffffu, sum1, 2);
    sum2 += __shfl_xor_sync(0xffffffffu, sum2, 1);
    sum2 += __shfl_xor_sync(0xffffffffu, sum2, 2);
    const float inv1 = 1.0f / sum1;
    const float inv2 = 1.0f / sum2;
    #pragma unroll
    for (int nt = 0; nt < 8; nt++) {
        sv[nt][0] *= inv1; sv[nt][1] *= inv1;
        sv[nt][2] *= inv2; sv[nt][3] *= inv2;
    }

    // ---- write attn probabilities ----
    {
        float* attn_b = attn_out + ((size_t)b * NHEAD + h) * (NTOK * NTOK);
        #pragma unroll
        for (int nt = 0; nt < 7; nt++) {   // nt=7 -> col0 >= 56, always OOB
            int col0 = nt * 8 + 2 * tig;
            int col1 = col0 + 1;
            if (i1 < NTOK) {
                if (col0 < NTOK) attn_b[i1 * 49 + col0] = sv[nt][0];
                if (col1 < NTOK) attn_b[i1 * 49 + col1] = sv[nt][1];
            }
            if (i2 < NTOK) {
                if (col0 < NTOK) attn_b[i2 * 49 + col0] = sv[nt][2];
                if (col1 < NTOK) attn_b[i2 * 49 + col1] = sv[nt][3];
            }
        }
    }

    // ---- O = P @ V  (P regs -> A fragments, hi/lo split) ----
    float ov[4][4];
    #pragma unroll
    for (int n = 0; n < 4; n++)
        #pragma unroll
        for (int e = 0; e < 4; e++) ov[n][e] = 0.0f;

    {
        uint32_t vb = smem_u32(vh) + (rofV * QP + cofV) * 2;
        uint32_t lb = smem_u32(vl) + (rofV * QP + cofV) * 2;
        #pragma unroll
        for (int t = 0; t < 4; t++) {
            // P fragments for keys 16t..16t+15
            uint32_t pH[4], pL[4];
            pH[0] = pk_split(sv[2*t][0],   sv[2*t][1],   pL[0]);
            pH[1] = pk_split(sv[2*t][2],   sv[2*t][3],   pL[1]);
            pH[2] = pk_split(sv[2*t+1][0], sv[2*t+1][1], pL[2]);
            pH[3] = pk_split(sv[2*t+1][2], sv[2*t+1][3], pL[3]);
            // V fragments (trans ldmatrix on row-major V)
            uint32_t vH0[4], vH1[4], vL0[4], vL1[4];
            uint32_t off = (uint32_t)(t * 16 * QP * 2);
            ldsm_x4_t(vH0, vb + off);
            ldsm_x4_t(vH1, vb + off + 32);
            ldsm_x4_t(vL0, lb + off);
            ldsm_x4_t(vL1, lb + off + 32);
            #pragma unroll
            for (int n = 0; n < 4; n++) {
                const uint32_t* bh = (n < 2 ? vH0 : vH1) + (n & 1) * 2;
                const uint32_t* bl = (n < 2 ? vL0 : vL1) + (n & 1) * 2;
                mma_bf16(ov[n], pH, bh);
                mma_bf16(ov[n], pH, bl);
                mma_bf16(ov[n], pL, bh);
            }
        }
    }

    // ---- write obuf as bf16 hi/lo ----
    #pragma unroll
    for (int n = 0; n < 4; n++) {
        int d0 = n * 8 + 2 * tig;
        if (i1 < NTOK) {
            size_t idx = ((size_t)b * NTOK + i1) * DIMC + h * HDIM + d0;
            uint32_t lo, hi = pk_split(ov[n][0], ov[n][1], lo);
            *(uint32_t*)(g_obuf_hi + idx) = hi;
            *(uint32_t*)(g_obuf_lo + idx) = lo;
        }
        if (i2 < NTOK) {
            size_t idx = ((size_t)b * NTOK + i2) * DIMC + h * HDIM + d0;
            uint32_t lo, hi = pk_split(ov[n][2], ov[n][3], lo);
            *(uint32_t*)(g_obuf_hi + idx) = hi;
            *(uint32_t*)(g_obuf_lo + idx) = lo;
        }
    }
}

// ---------------------------------------------------------------------------
extern "C" void kernel_launch(void* const* d_in, const int* in_sizes, int n_in,
                              void* d_out, int out_size)
{
    const float* x      = (const float*)d_in[0];
    const float* mask   = (const float*)d_in[1];
    const float* qkv_w  = (const float*)d_in[2];
    const float* qkv_b  = (const float*)d_in[3];
    const float* q_rpe  = (const float*)d_in[4];
    const float* k_rpe  = (const float*)d_in[5];
    const float* proj_w = (const float*)d_in[6];
    const float* proj_b = (const float*)d_in[7];
    // d_in[8] = rpe_indices: recomputed analytically in-kernel

    float* out  = (float*)d_out;
    float* attn = out + (size_t)TOKENS * DIMC;

    void *qkv_p, *xhi, *xlo, *whq, *wlq, *whp, *wlp, *ohi, *olo;
    cudaGetSymbolAddress(&qkv_p, g_qkv);
    cudaGetSymbolAddress(&xhi, g_x_hi);
    cudaGetSymbolAddress(&xlo, g_x_lo);
    cudaGetSymbolAddress(&whq, g_wqkv_hi);
    cudaGetSymbolAddress(&wlq, g_wqkv_lo);
    cudaGetSymbolAddress(&whp, g_wproj_hi);
    cudaGetSymbolAddress(&wlp, g_wproj_lo);
    cudaGetSymbolAddress(&ohi, g_obuf_hi);
    cudaGetSymbolAddress(&olo, g_obuf_lo);

    // K0: splits
    splitw_kernel<<<(DIMC * QKVCOLS + 255) / 256, 256>>>(
        qkv_w, (__nv_bfloat16*)whq, (__nv_bfloat16*)wlq, DIMC, QKVCOLS);
    splitw_kernel<<<(DIMC * DIMC + 255) / 256, 256>>>(
        proj_w, (__nv_bfloat16*)whp, (__nv_bfloat16*)wlp, DIMC, DIMC);
    {
        int n4 = TOKENS * DIMC / 4;
        splitf_kernel<<<(n4 + 255) / 256, 256>>>(
            x, (__nv_bfloat16*)xhi, (__nv_bfloat16*)xlo, n4);
    }

    // K1: QKV projection (HMMA) — q cols pre-scaled
    {
        dim3 grid(QKVCOLS / 64, TOKENS / 128);
        mma_gemm_kernel<<<grid, 256>>>(
            (const __nv_bfloat16*)xhi, (const __nv_bfloat16*)xlo,
            (const __nv_bfloat16*)whq, (const __nv_bfloat16*)wlq,
            qkv_b, (float*)qkv_p, QKVCOLS, DIMC, QSCALE);
    }
    // K2a: bias GEMM (+mask)
    {
        dim3 grid(NHEAD * NTOK, B_WIN / 128);
        bias_kernel<<<grid, 256>>>(q_rpe, k_rpe, mask);
    }
    // K2b: attention (HMMA)
    {
        dim3 grid(NHEAD, B_WIN);
        attn3_kernel<<<grid, 128>>>(attn);
    }
    // K3: output projection (HMMA)
    {
        dim3 grid(DIMC / 64, TOKENS / 128);
        mma_gemm_kernel<<<grid, 256>>>(
            (const __nv_bfloat16*)ohi, (const __nv_bfloat16*)olo,
            (const __nv_bfloat16*)whp, (const __nv_bfloat16*)wlp,
            proj_b, out, DIMC, 0, 1.0f);
    }
}

// round 9
// speedup vs baseline: 2.1778x; 1.2015x over previous
#include <cuda_runtime.h>
#include <cuda_bf16.h>
#include <cstdint>

// ---------------------------------------------------------------------------
// WindowAttentionConvRpe: B=4096 windows, N=49, DIM=192, NH=6, HD=32, T=169.
//   K0 : split weights (transposed [N][K]) and x into bf16 hi/lo
//   K1 : QKV = X @ qkv_w + qkv_b          (HMMA bf16 3-term split, ldmatrix)
//   K2a: BIAS = [q;k] . gathered-RPE GEMM + window mask (SIMT, 56-padded rows)
//   K2b: attention, HMMA flash-style, bias loaded direct-to-registers
//   K3 : OUT = O @ proj_w + proj_b        (HMMA)
// tcgen05 unavailable (PTX target sm_103 w/o 'a'); mma.sync path instead.
// ---------------------------------------------------------------------------

#define B_WIN   4096
#define NTOK    49
#define DIMC    192
#define NHEAD   6
#define HDIM    32
#define TSZ     169
#define TOKENS  (B_WIN * NTOK)
#define QKVCOLS (3 * DIMC)
#define QSCALE  0.17677669529663687f
#define BPAD    56

__device__ float g_qkv [(size_t)TOKENS * QKVCOLS];
__device__ float g_bias[(size_t)B_WIN * NHEAD * NTOK * BPAD];
__device__ __nv_bfloat16 g_x_hi [(size_t)TOKENS * DIMC];
__device__ __nv_bfloat16 g_x_lo [(size_t)TOKENS * DIMC];
__device__ __nv_bfloat16 g_obuf_hi[(size_t)TOKENS * DIMC];
__device__ __nv_bfloat16 g_obuf_lo[(size_t)TOKENS * DIMC];
__device__ __nv_bfloat16 g_wqkv_hi[QKVCOLS * DIMC];   // [576][192] transposed
__device__ __nv_bfloat16 g_wqkv_lo[QKVCOLS * DIMC];
__device__ __nv_bfloat16 g_wproj_hi[DIMC * DIMC];     // [192][192] transposed
__device__ __nv_bfloat16 g_wproj_lo[DIMC * DIMC];

// ======================= K0a: weight transpose + split =====================
__global__ void splitw_kernel(const float* __restrict__ w,
                              __nv_bfloat16* __restrict__ thi,
                              __nv_bfloat16* __restrict__ tlo, int K, int N)
{
    int i = blockIdx.x * 256 + threadIdx.x;
    if (i >= K * N) return;
    int n = i / K, k = i % K;
    float v = w[(size_t)k * N + n];
    __nv_bfloat16 h = __float2bfloat16(v);
    thi[i] = h;
    tlo[i] = __float2bfloat16(v - __bfloat162float(h));
}

// ======================= K0b: activation split =============================
__global__ void splitf_kernel(const float* __restrict__ src,
                              __nv_bfloat16* __restrict__ hi,
                              __nv_bfloat16* __restrict__ lo, int n4)
{
    int i = blockIdx.x * 256 + threadIdx.x;
    if (i >= n4) return;
    float4 v = ((const float4*)src)[i];
    float vv[4] = {v.x, v.y, v.z, v.w};
    union { uint2 q; __nv_bfloat16 h[4]; } H, L;
    #pragma unroll
    for (int e = 0; e < 4; e++) {
        H.h[e] = __float2bfloat16(vv[e]);
        L.h[e] = __float2bfloat16(vv[e] - __bfloat162float(H.h[e]));
    }
    ((uint2*)hi)[i] = H.q;
    ((uint2*)lo)[i] = L.q;
}

// ======================= mma / ldmatrix helpers ============================
__device__ __forceinline__ void mma_bf16(float* d, const uint32_t* a,
                                         const uint32_t* b)
{
    asm volatile(
        "mma.sync.aligned.m16n8k16.row.col.f32.bf16.bf16.f32 "
        "{%0,%1,%2,%3}, {%4,%5,%6,%7}, {%8,%9}, {%0,%1,%2,%3};"
        : "+f"(d[0]), "+f"(d[1]), "+f"(d[2]), "+f"(d[3])
        : "r"(a[0]), "r"(a[1]), "r"(a[2]), "r"(a[3]),
          "r"(b[0]), "r"(b[1]));
}
__device__ __forceinline__ void ldsm_x4(uint32_t* r, uint32_t saddr)
{
    asm volatile("ldmatrix.sync.aligned.m8n8.x4.shared.b16 {%0,%1,%2,%3}, [%4];"
        : "=r"(r[0]), "=r"(r[1]), "=r"(r[2]), "=r"(r[3]) : "r"(saddr));
}
__device__ __forceinline__ void ldsm_x4_t(uint32_t* r, uint32_t saddr)
{
    asm volatile("ldmatrix.sync.aligned.m8n8.x4.trans.shared.b16 {%0,%1,%2,%3}, [%4];"
        : "=r"(r[0]), "=r"(r[1]), "=r"(r[2]), "=r"(r[3]) : "r"(saddr));
}
__device__ __forceinline__ uint32_t smem_u32(const void* p) {
    uint32_t a;
    asm("{ .reg .u64 t; cvta.to.shared.u64 t, %1; cvt.u32.u64 %0, t; }"
        : "=r"(a) : "l"(p));
    return a;
}
__device__ __forceinline__ uint32_t pk_split(float a, float b, uint32_t& lo) {
    __nv_bfloat16 ha = __float2bfloat16(a), hb = __float2bfloat16(b);
    __nv_bfloat16 la = __float2bfloat16(a - __bfloat162float(ha));
    __nv_bfloat16 lb = __float2bfloat16(b - __bfloat162float(hb));
    __nv_bfloat162 H; H.x = ha; H.y = hb;
    __nv_bfloat162 L; L.x = la; L.y = lb;
    lo = *(uint32_t*)&L;
    return *(uint32_t*)&H;
}

// ======================= K1/K3: HMMA split GEMM ============================
// Block 256M x 64N, 8 warps (4M x 2N), warp tile 64x32 (4 m16 x 4 n8).
// ldsm.x4 per warp per k16-step: A 8 (hi+lo), B 4 -> 12 per 48 HMMA.
#define APAD 40
#define GSM_AH 0
#define GSM_AL (256 * APAD * 2)
#define GSM_BH (2 * 256 * APAD * 2)
#define GSM_BL (GSM_BH + 64 * APAD * 2)
#define GSM_TOTAL (GSM_BL + 64 * APAD * 2)

__global__ __launch_bounds__(256) void mma_gemm_kernel(
    const __nv_bfloat16* __restrict__ Ahi, const __nv_bfloat16* __restrict__ Alo,
    const __nv_bfloat16* __restrict__ Bhi, const __nv_bfloat16* __restrict__ Blo,
    const float* __restrict__ bias, float* __restrict__ C,
    int Nld, int scale_limit, float scale)
{
    extern __shared__ char gsm[];
    __nv_bfloat16* sAh = (__nv_bfloat16*)(gsm + GSM_AH);
    __nv_bfloat16* sAl = (__nv_bfloat16*)(gsm + GSM_AL);
    __nv_bfloat16* sBh = (__nv_bfloat16*)(gsm + GSM_BH);
    __nv_bfloat16* sBl = (__nv_bfloat16*)(gsm + GSM_BL);

    const int tid  = threadIdx.x;
    const int lane = tid & 31;
    const int wid  = tid >> 5;
    const int warpM = wid & 3;       // 4 warps in M, 64 rows each
    const int warpN = wid >> 2;      // 2 warps in N, 32 cols each
    const int g   = lane >> 2;
    const int tig = lane & 3;
    const int m0 = blockIdx.y * 256;
    const int n0 = blockIdx.x * 64;

    float acc[4][4][4];
    #pragma unroll
    for (int mt = 0; mt < 4; mt++)
        #pragma unroll
        for (int nt = 0; nt < 4; nt++)
            #pragma unroll
            for (int e = 0; e < 4; e++) acc[mt][nt][e] = 0.0f;

    const int rofA = ((lane >> 3) & 1) * 8 + (lane & 7);
    const int kofA = ((lane >> 4) & 1) * 8;
    const int rofB = ((lane >> 4) & 1) * 8 + (lane & 7);
    const int kofB = ((lane >> 3) & 1) * 8;

    const uint32_t aHiB = smem_u32(sAh) + ((warpM * 64 + rofA) * APAD + kofA) * 2;
    const uint32_t aLoB = smem_u32(sAl) + ((warpM * 64 + rofA) * APAD + kofA) * 2;
    const uint32_t bHiB = smem_u32(sBh) + ((warpN * 32 + rofB) * APAD + kofB) * 2;
    const uint32_t bLoB = smem_u32(sBl) + ((warpN * 32 + rofB) * APAD + kofB) * 2;

    for (int k0 = 0; k0 < 192; k0 += 32) {
        // A tile: 256 rows x 32 cols (4 uint4/row), hi+lo
        #pragma unroll
        for (int r = 0; r < 4; r++) {
            int c = tid + r * 256;
            int row = c >> 2, u = c & 3;
            size_t src = (size_t)(m0 + row) * 192 + k0 + u * 8;
            *(uint4*)(sAh + row * APAD + u * 8) = *(const uint4*)(Ahi + src);
            *(uint4*)(sAl + row * APAD + u * 8) = *(const uint4*)(Alo + src);
        }
        // B tile: 64 rows x 32 cols, hi+lo
        {
            int row = tid >> 2, u = tid & 3;
            size_t src = (size_t)(n0 + row) * 192 + k0 + u * 8;
            *(uint4*)(sBh + row * APAD + u * 8) = *(const uint4*)(Bhi + src);
            *(uint4*)(sBl + row * APAD + u * 8) = *(const uint4*)(Blo + src);
        }
        __syncthreads();

        #pragma unroll
        for (int s = 0; s < 2; s++) {
            uint32_t ahi[4][4], alo[4][4], bhi[2][4], blo[2][4];
            #pragma unroll
            for (int mt = 0; mt < 4; mt++) {
                uint32_t off = (uint32_t)((mt * 16 * APAD + s * 16) * 2);
                ldsm_x4(ahi[mt], aHiB + off);
                ldsm_x4(alo[mt], aLoB + off);
            }
            #pragma unroll
            for (int p = 0; p < 2; p++) {
                uint32_t off = (uint32_t)((p * 16 * APAD + s * 16) * 2);
                ldsm_x4(bhi[p], bHiB + off);
                ldsm_x4(blo[p], bLoB + off);
            }
            #pragma unroll
            for (int mt = 0; mt < 4; mt++)
                #pragma unroll
                for (int nt = 0; nt < 4; nt++) {
                    const uint32_t* bh = &bhi[nt >> 1][(nt & 1) * 2];
                    const uint32_t* bl = &blo[nt >> 1][(nt & 1) * 2];
                    mma_bf16(acc[mt][nt], ahi[mt], bh);
                    mma_bf16(acc[mt][nt], ahi[mt], bl);
                    mma_bf16(acc[mt][nt], alo[mt], bh);
                }
        }
        __syncthreads();
    }

    #pragma unroll
    for (int mt = 0; mt < 4; mt++) {
        int row = m0 + warpM * 64 + mt * 16 + g;
        #pragma unroll
        for (int nt = 0; nt < 4; nt++) {
            int col = n0 + warpN * 32 + nt * 8 + 2 * tig;
            float b0 = bias[col], b1 = bias[col + 1];
            float c0 = acc[mt][nt][0] + b0;
            float c1 = acc[mt][nt][1] + b1;
            float c2 = acc[mt][nt][2] + b0;
            float c3 = acc[mt][nt][3] + b1;
            if (col < scale_limit) {
                c0 *= scale; c1 *= scale; c2 *= scale; c3 *= scale;
            }
            *(float2*)(C + (size_t)row * Nld + col)       = make_float2(c0, c1);
            *(float2*)(C + (size_t)(row + 8) * Nld + col) = make_float2(c2, c3);
        }
    }
}

// ======================= K2a: bias GEMM + mask fuse (SIMT) =================
// writes 56-padded rows; pad columns (49..55) zero-filled.
__global__ __launch_bounds__(256) void bias_kernel(
    const float* __restrict__ q_rpe, const float* __restrict__ k_rpe,
    const float* __restrict__ mask)
{
    __shared__ float A_s[64][128];
    __shared__ float G_s[64][64];

    const int hi = blockIdx.x;
    const int h  = hi / NTOK;
    const int i  = hi % NTOK;
    const int ri = i / 7, ci = i % 7;
    const int m0 = blockIdx.y * 128;
    const int tid = threadIdx.x;

    for (int f = tid; f < 8 * 128; f += 256) {
        int bl = f & 127;
        int g4 = f >> 7;
        size_t row = ((size_t)(m0 + bl) * NTOK + i) * QKVCOLS + h * HDIM;
        float4 qv = *(const float4*)(g_qkv + row + g4 * 4);
        A_s[g4 * 4 + 0][bl] = qv.x; A_s[g4 * 4 + 1][bl] = qv.y;
        A_s[g4 * 4 + 2][bl] = qv.z; A_s[g4 * 4 + 3][bl] = qv.w;
        float4 kv = *(const float4*)(g_qkv + row + DIMC + g4 * 4);
        A_s[32 + g4 * 4 + 0][bl] = kv.x; A_s[32 + g4 * 4 + 1][bl] = kv.y;
        A_s[32 + g4 * 4 + 2][bl] = kv.z; A_s[32 + g4 * 4 + 3][bl] = kv.w;
    }
    for (int f = tid; f < 64 * 64; f += 256) {
        int d = f >> 6, j = f & 63;
        float val = 0.0f;
        if (j < NTOK) {
            int t = (ri - j / 7 + 6) * 13 + (ci - j % 7 + 6);
            val = (d < HDIM) ? q_rpe[(h * HDIM + d) * TSZ + t]
                             : k_rpe[(h * HDIM + (d - 32)) * TSZ + t];
        }
        G_s[d][j] = val;
    }
    __syncthreads();

    const int tx = tid & 7;
    const int ty = tid >> 3;

    float acc[4][8];
    #pragma unroll
    for (int r = 0; r < 4; r++)
        #pragma unroll
        for (int c = 0; c < 8; c++) acc[r][c] = 0.0f;

    #pragma unroll 16
    for (int d = 0; d < 64; d++) {
        float4 a4 = *(float4*)&A_s[d][ty * 4];
        float4 g0 = *(float4*)&G_s[d][tx * 8];
        float4 g1 = *(float4*)&G_s[d][tx * 8 + 4];
        float a[4] = {a4.x, a4.y, a4.z, a4.w};
        float g[8] = {g0.x, g0.y, g0.z, g0.w, g1.x, g1.y, g1.z, g1.w};
        #pragma unroll
        for (int r = 0; r < 4; r++)
            #pragma unroll
            for (int c = 0; c < 8; c++)
                acc[r][c] += a[r] * g[c];
    }

    #pragma unroll
    for (int r = 0; r < 4; r++) {
        int bw = m0 + ty * 4 + r;
        size_t base = (((size_t)bw * NHEAD + h) * NTOK + i) * BPAD;
        const float* mrow = mask + ((size_t)(bw & 63) * NTOK + i) * NTOK;
        #pragma unroll
        for (int c = 0; c < 8; c++) {
            int j = tx * 8 + c;
            if (j < BPAD)
                g_bias[base + j] = (j < NTOK) ? (acc[r][c] + mrow[j]) : 0.0f;
        }
    }
}

// ======================= K2b: attention (HMMA flash-style) =================
// One (b,h) per block, 128 threads (4 warps, 16 rows each). Bias loaded
// directly to registers from the 56-padded layout (no smem staging).
#define QP 40
__global__ __launch_bounds__(128) void attn3_kernel(float* __restrict__ attn_out)
{
    __shared__ __align__(16) __nv_bfloat16 qh[64 * QP], ql[64 * QP];
    __shared__ __align__(16) __nv_bfloat16 kh[64 * QP], kl[64 * QP];
    __shared__ __align__(16) __nv_bfloat16 vh[64 * QP], vl[64 * QP];

    const int h = blockIdx.x;
    const int b = blockIdx.y;
    const int tid  = threadIdx.x;
    const int lane = tid & 31;
    const int warp = tid >> 5;
    const int g   = lane >> 2;
    const int tig = lane & 3;

    // ---- stage q,k,v as bf16 hi/lo (rows 49-63 zeroed) ----
    for (int f = tid; f < 64 * 8; f += 128) {
        int i = f >> 3, c4 = (f & 7) * 4;
        float4 qv = {0,0,0,0}, kv = {0,0,0,0}, vv = {0,0,0,0};
        if (i < NTOK) {
            size_t row = ((size_t)b * NTOK + i) * QKVCOLS + h * HDIM;
            qv = *(const float4*)(g_qkv + row + c4);
            kv = *(const float4*)(g_qkv + row + DIMC + c4);
            vv = *(const float4*)(g_qkv + row + 2 * DIMC + c4);
        }
        float qa[4] = {qv.x, qv.y, qv.z, qv.w};
        float ka[4] = {kv.x, kv.y, kv.z, kv.w};
        float va[4] = {vv.x, vv.y, vv.z, vv.w};
        union { uint2 u; __nv_bfloat16 e[4]; } QH, QL, KH, KL, VH, VL;
        #pragma unroll
        for (int e = 0; e < 4; e++) {
            QH.e[e] = __float2bfloat16(qa[e]);
            QL.e[e] = __float2bfloat16(qa[e] - __bfloat162float(QH.e[e]));
            KH.e[e] = __float2bfloat16(ka[e]);
            KL.e[e] = __float2bfloat16(ka[e] - __bfloat162float(KH.e[e]));
            VH.e[e] = __float2bfloat16(va[e]);
            VL.e[e] = __float2bfloat16(va[e] - __bfloat162float(VH.e[e]));
        }
        int o = i * QP + c4;
        *(uint2*)(qh + o) = QH.u; *(uint2*)(ql + o) = QL.u;
        *(uint2*)(kh + o) = KH.u; *(uint2*)(kl + o) = KL.u;
        *(uint2*)(vh + o) = VH.u; *(uint2*)(vl + o) = VL.u;
    }
    __syncthreads();

    const int m0 = warp * 16;
    const int i1 = m0 + g;
    const int i2 = m0 + g + 8;

    // ---- bias(+mask) direct to registers (row-clamped; pads are zero) ----
    const float* brow0 = g_bias + ((size_t)b * NHEAD + h) * (NTOK * BPAD);
    const int r1 = min(i1, NTOK - 1);
    const int r2 = min(i2, NTOK - 1);
    float2 bv1[7], bv2[7];
    #pragma unroll
    for (int nt = 0; nt < 7; nt++) {
        int col0 = nt * 8 + 2 * tig;
        bv1[nt] = *(const float2*)(brow0 + r1 * BPAD + col0);
        bv2[nt] = *(const float2*)(brow0 + r2 * BPAD + col0);
    }

    // ldmatrix lane offsets
    const int rofA = ((lane >> 3) & 1) * 8 + (lane & 7);
    const int kofA = ((lane >> 4) & 1) * 8;
    const int rofB = ((lane >> 4) & 1) * 8 + (lane & 7);
    const int kofB = ((lane >> 3) & 1) * 8;
    const int rofV = ((lane >> 3) & 1) * 8 + (lane & 7);
    const int cofV = ((lane >> 4) & 1) * 8;

    // ---- S = Q @ K^T ----
    uint32_t aQh[2][4], aQl[2][4];
    {
        uint32_t qb = smem_u32(qh) + ((m0 + rofA) * QP + kofA) * 2;
        uint32_t lb = smem_u32(ql) + ((m0 + rofA) * QP + kofA) * 2;
        #pragma unroll
        for (int s = 0; s < 2; s++) {
            ldsm_x4(aQh[s], qb + s * 32);
            ldsm_x4(aQl[s], lb + s * 32);
        }
    }
    float sv[8][4];
    #pragma unroll
    for (int nt = 0; nt < 8; nt++)
        #pragma unroll
        for (int e = 0; e < 4; e++) sv[nt][e] = 0.0f;

    {
        uint32_t kb = smem_u32(kh) + (rofB * QP + kofB) * 2;
        uint32_t lb = smem_u32(kl) + (rofB * QP + kofB) * 2;
        #pragma unroll
        for (int p = 0; p < 4; p++) {
            uint32_t kH[2][4], kL[2][4];
            #pragma unroll
            for (int s = 0; s < 2; s++) {
                uint32_t off = (uint32_t)((p * 16 * QP + s * 16) * 2);
                ldsm_x4(kH[s], kb + off);
                ldsm_x4(kL[s], lb + off);
            }
            #pragma unroll
            for (int half = 0; half < 2; half++) {
                int nt = 2 * p + half;
                #pragma unroll
                for (int s = 0; s < 2; s++) {
                    mma_bf16(sv[nt], aQh[s], &kH[s][half * 2]);
                    mma_bf16(sv[nt], aQh[s], &kL[s][half * 2]);
                    mma_bf16(sv[nt], aQl[s], &kH[s][half * 2]);
                }
            }
        }
    }

    // ---- bias + softmax ----
    float mx1 = -3.0e38f, mx2 = -3.0e38f;
    #pragma unroll
    for (int nt = 0; nt < 8; nt++) {
        int col0 = nt * 8 + 2 * tig;
        int col1 = col0 + 1;
        float b00 = (nt < 7) ? bv1[nt].x : 0.0f;
        float b01 = (nt < 7) ? bv1[nt].y : 0.0f;
        float b10 = (nt < 7) ? bv2[nt].x : 0.0f;
        float b11 = (nt < 7) ? bv2[nt].y : 0.0f;
        float v0 = sv[nt][0] + b00; if (col0 >= NTOK) v0 = -1.0e30f;
        float v1 = sv[nt][1] + b01; if (col1 >= NTOK) v1 = -1.0e30f;
        float v2 = sv[nt][2] + b10; if (col0 >= NTOK) v2 = -1.0e30f;
        float v3 = sv[nt][3] + b11; if (col1 >= NTOK) v3 = -1.0e30f;
        sv[nt][0] = v0; sv[nt][1] = v1; sv[nt][2] = v2; sv[nt][3] = v3;
        mx1 = fmaxf(mx1, fmaxf(v0, v1));
        mx2 = fmaxf(mx2, fmaxf(v2, v3));
    }
    mx1 = fmaxf(mx1, __shfl_xor_sync(0xffffffffu, mx1, 1));
    mx1 = fmaxf(mx1, __shfl_xor_sync(0xffffffffu, mx1, 2));
    mx2 = fmaxf(mx2, __shfl_xor_sync(0xffffffffu, mx2, 1));
    mx2 = fmaxf(mx2, __shfl_xor_sync(0xffffffffu, mx2, 2));

    float sum1 = 0.0f, sum2 = 0.0f;
    #pragma unroll
    for (int nt = 0; nt < 8; nt++) {
        float e0 = __expf(sv[nt][0] - mx1);
        float e1 = __expf(sv[nt][1] - mx1);
        float e2 = __expf(sv[nt][2] - mx2);
        float e3 = __expf(sv[nt][3] - mx2);
        sv[nt][0] = e0; sv[nt][1] = e1; sv[nt][2] = e2; sv[nt][3] = e3;
        sum1 += e0 + e1;
        sum2 += e2 + e3;
    }
    sum1 += __shfl_xor_sync(0xffffffffu, sum1, 1);
    sum1 += __shfl_xor_sync(0xffffffffu, sum1, 2);
    sum2 += __shfl_xor_sync(0xffffffffu, sum2, 1);
    sum2 += __shfl_xor_sync(0xffffffffu, sum2, 2);
    const float inv1 = 1.0f / sum1;
    const float inv2 = 1.0f / sum2;
    #pragma unroll
    for (int nt = 0; nt < 8; nt++) {
        sv[nt][0] *= inv1; sv[nt][1] *= inv1;
        sv[nt][2] *= inv2; sv[nt][3] *= inv2;
    }

    // ---- write attn probabilities ----
    {
        float* attn_b = attn_out + ((size_t)b * NHEAD + h) * (NTOK * NTOK);
        #pragma unroll
        for (int nt = 0; nt < 7; nt++) {
            int col0 = nt * 8 + 2 * tig;
            int col1 = col0 + 1;
            if (i1 < NTOK) {
                if (col0 < NTOK) attn_b[i1 * 49 + col0] = sv[nt][0];
                if (col1 < NTOK) attn_b[i1 * 49 + col1] = sv[nt][1];
            }
            if (i2 < NTOK) {
                if (col0 < NTOK) attn_b[i2 * 49 + col0] = sv[nt][2];
                if (col1 < NTOK) attn_b[i2 * 49 + col1] = sv[nt][3];
            }
        }
    }

    // ---- O = P @ V ----
    float ov[4][4];
    #pragma unroll
    for (int n = 0; n < 4; n++)
        #pragma unroll
        for (int e = 0; e < 4; e++) ov[n][e] = 0.0f;

    {
        uint32_t vb = smem_u32(vh) + (rofV * QP + cofV) * 2;
        uint32_t lb = smem_u32(vl) + (rofV * QP + cofV) * 2;
        #pragma unroll
        for (int t = 0; t < 4; t++) {
            uint32_t pH[4], pL[4];
            pH[0] = pk_split(sv[2*t][0],   sv[2*t][1],   pL[0]);
            pH[1] = pk_split(sv[2*t][2],   sv[2*t][3],   pL[1]);
            pH[2] = pk_split(sv[2*t+1][0], sv[2*t+1][1], pL[2]);
            pH[3] = pk_split(sv[2*t+1][2], sv[2*t+1][3], pL[3]);
            uint32_t vH0[4], vH1[4], vL0[4], vL1[4];
            uint32_t off = (uint32_t)(t * 16 * QP * 2);
            ldsm_x4_t(vH0, vb + off);
            ldsm_x4_t(vH1, vb + off + 32);
            ldsm_x4_t(vL0, lb + off);
            ldsm_x4_t(vL1, lb + off + 32);
            #pragma unroll
            for (int n = 0; n < 4; n++) {
                const uint32_t* bh = (n < 2 ? vH0 : vH1) + (n & 1) * 2;
                const uint32_t* bl = (n < 2 ? vL0 : vL1) + (n & 1) * 2;
                mma_bf16(ov[n], pH, bh);
                mma_bf16(ov[n], pH, bl);
                mma_bf16(ov[n], pL, bh);
            }
        }
    }

    // ---- write obuf as bf16 hi/lo ----
    #pragma unroll
    for (int n = 0; n < 4; n++) {
        int d0 = n * 8 + 2 * tig;
        if (i1 < NTOK) {
            size_t idx = ((size_t)b * NTOK + i1) * DIMC + h * HDIM + d0;
            uint32_t lo, hi = pk_split(ov[n][0], ov[n][1], lo);
            *(uint32_t*)(g_obuf_hi + idx) = hi;
            *(uint32_t*)(g_obuf_lo + idx) = lo;
        }
        if (i2 < NTOK) {
            size_t idx = ((size_t)b * NTOK + i2) * DIMC + h * HDIM + d0;
            uint32_t lo, hi = pk_split(ov[n][2], ov[n][3], lo);
            *(uint32_t*)(g_obuf_hi + idx) = hi;
            *(uint32_t*)(g_obuf_lo + idx) = lo;
        }
    }
}

// ---------------------------------------------------------------------------
extern "C" void kernel_launch(void* const* d_in, const int* in_sizes, int n_in,
                              void* d_out, int out_size)
{
    const float* x      = (const float*)d_in[0];
    const float* mask   = (const float*)d_in[1];
    const float* qkv_w  = (const float*)d_in[2];
    const float* qkv_b  = (const float*)d_in[3];
    const float* q_rpe  = (const float*)d_in[4];
    const float* k_rpe  = (const float*)d_in[5];
    const float* proj_w = (const float*)d_in[6];
    const float* proj_b = (const float*)d_in[7];
    // d_in[8] = rpe_indices: recomputed analytically in-kernel

    float* out  = (float*)d_out;
    float* attn = out + (size_t)TOKENS * DIMC;

    void *qkv_p, *xhi, *xlo, *whq, *wlq, *whp, *wlp, *ohi, *olo;
    cudaGetSymbolAddress(&qkv_p, g_qkv);
    cudaGetSymbolAddress(&xhi, g_x_hi);
    cudaGetSymbolAddress(&xlo, g_x_lo);
    cudaGetSymbolAddress(&whq, g_wqkv_hi);
    cudaGetSymbolAddress(&wlq, g_wqkv_lo);
    cudaGetSymbolAddress(&whp, g_wproj_hi);
    cudaGetSymbolAddress(&wlp, g_wproj_lo);
    cudaGetSymbolAddress(&ohi, g_obuf_hi);
    cudaGetSymbolAddress(&olo, g_obuf_lo);

    cudaFuncSetAttribute(mma_gemm_kernel,
                         cudaFuncAttributeMaxDynamicSharedMemorySize, GSM_TOTAL);

    // K0: splits
    splitw_kernel<<<(DIMC * QKVCOLS + 255) / 256, 256>>>(
        qkv_w, (__nv_bfloat16*)whq, (__nv_bfloat16*)wlq, DIMC, QKVCOLS);
    splitw_kernel<<<(DIMC * DIMC + 255) / 256, 256>>>(
        proj_w, (__nv_bfloat16*)whp, (__nv_bfloat16*)wlp, DIMC, DIMC);
    {
        int n4 = TOKENS * DIMC / 4;
        splitf_kernel<<<(n4 + 255) / 256, 256>>>(
            x, (__nv_bfloat16*)xhi, (__nv_bfloat16*)xlo, n4);
    }

    // K1: QKV projection (HMMA) — q cols pre-scaled
    {
        dim3 grid(QKVCOLS / 64, TOKENS / 256);
        mma_gemm_kernel<<<grid, 256, GSM_TOTAL>>>(
            (const __nv_bfloat16*)xhi, (const __nv_bfloat16*)xlo,
            (const __nv_bfloat16*)whq, (const __nv_bfloat16*)wlq,
            qkv_b, (float*)qkv_p, QKVCOLS, DIMC, QSCALE);
    }
    // K2a: bias GEMM (+mask), 56-padded rows
    {
        dim3 grid(NHEAD * NTOK, B_WIN / 128);
        bias_kernel<<<grid, 256>>>(q_rpe, k_rpe, mask);
    }
    // K2b: attention (HMMA)
    {
        dim3 grid(NHEAD, B_WIN);
        attn3_kernel<<<grid, 128>>>(attn);
    }
    // K3: output projection (HMMA)
    {
        dim3 grid(DIMC / 64, TOKENS / 256);
        mma_gemm_kernel<<<grid, 256, GSM_TOTAL>>>(
            (const __nv_bfloat16*)ohi, (const __nv_bfloat16*)olo,
            (const __nv_bfloat16*)whp, (const __nv_bfloat16*)wlp,
            proj_b, out, DIMC, 0, 1.0f);
    }
}